// round 11
// baseline (speedup 1.0000x reference)
#include <cuda_runtime.h>
#include <cuda_fp16.h>
#include <cstdint>

#define NPTS 8192
#define KNN  8

// ---------------- scratch (device globals: no allocations allowed) ----------
__device__ int   g_knn[NPTS * KNN];
__device__ unsigned short g_x1h[NPTS * 128];  // edgeconv1 output fp16 [i][k]
__device__ float g_A  [NPTS * 128];           // x1 @ (W3a - W3b) + b3
__device__ float g_B  [NPTS * 128];           // x1 @ W3b
__device__ unsigned short g_w2h[128 * 64];    // W2^T fp16 [c][u]
__device__ unsigned short g_w3h[256 * 128];   // [Wd^T ; Wb^T] fp16 [n][k]
__device__ unsigned short g_w4h[256 * 128];   // W4^T fp16 [c][k]

// ---------------- helpers ----------------------------------------------------
__device__ __forceinline__ uint32_t smem_u32(const void* p) {
    uint32_t a;
    asm("{ .reg .u64 t; cvta.to.shared.u64 t, %1; cvt.u32.u64 %0, t; }"
        : "=r"(a) : "l"(p));
    return a;
}

// fp16 split: f = h + l, h = fp16(f), l = fp16(f - h)
__device__ __forceinline__ void h16_split(float f, __half& h, __half& l) {
    h = __float2half_rn(f);
    l = __float2half_rn(f - __half2float(h));
}

// ---------------- Kernel 1: tensor-core KNN + weight conversion -------------
// Per CTA: 64 queries. 8 warps = 4 m-groups x 2 candidate-halves.
// d' = |c|^2 - 2 q.c  computed by 3-pass split-fp16 mma (|c|^2 folded into k-slot 3).
#define QB   64
#define TN   128
#define PADC 24
__global__ __launch_bounds__(256) void knn_kernel(
    const float* __restrict__ pts,
    const float* __restrict__ W2, const float* __restrict__ W3,
    const float* __restrict__ W4)
{
    // ---- weight fp16 conversion prologue (32768 threads == exactly cover) ----
    {
        const int gt = blockIdx.x * 256 + threadIdx.x;
        if (gt < 8192) {                  // g_w2h[c*64+u] = W2[u][c]
            int c = gt >> 6, u = gt & 63;
            g_w2h[gt] = __half_as_ushort(__float2half_rn(W2[u*128 + c]));
        }
        if (gt < 16384) {                 // W3 -> [Wd^T ; Wb^T]
            int k = gt >> 7, c = gt & 127;
            float wa = W3[k*128 + c];
            float wb = W3[(k+128)*128 + c];
            g_w3h[c*128 + k]       = __half_as_ushort(__float2half_rn(wa - wb));
            g_w3h[(128+c)*128 + k] = __half_as_ushort(__float2half_rn(wb));
        }
        {                                  // g_w4h[c*128+k] = W4[k][c]
            int k = gt >> 8, c = gt & 255;
            g_w4h[c*128 + k] = __half_as_ushort(__float2half_rn(W4[k*256 + c]));
        }
    }

    __shared__ __half sQh[QB * PADC], sQl[QB * PADC];
    __shared__ __half sCh[2][TN * PADC], sCl[2][TN * PADC];
    __shared__ unsigned long long sMrg[2][QB][8];

    const int t    = threadIdx.x;
    const int lane = t & 31;
    const int w    = t >> 5;
    const int mg   = w & 3;            // m-group (16 queries)
    const int ch   = w >> 2;           // candidate half (0/1)
    const int qi0  = blockIdx.x * QB;

    // ---- stage Q tiles: A = split(-2q), k-slot3: hi=1, lo=0, rest 0 ----
    if (t < QB) {
        const int qi = qi0 + t;
        float x = pts[qi*3+0], y = pts[qi*3+1], z = pts[qi*3+2];
        __half hx, lx, hy, ly, hz, lz;
        h16_split(-2.0f*x, hx, lx);
        h16_split(-2.0f*y, hy, ly);
        h16_split(-2.0f*z, hz, lz);
        __half* qh = sQh + t * PADC;
        __half* ql = sQl + t * PADC;
        qh[0]=hx; qh[1]=hy; qh[2]=hz; qh[3]=__float2half_rn(1.0f);
        ql[0]=lx; ql[1]=ly; ql[2]=lz; ql[3]=__ushort_as_half(0);
        #pragma unroll
        for (int s = 4; s < 16; s++) {
            qh[s] = __ushort_as_half(0);
            ql[s] = __ushort_as_half(0);
        }
    }
    __syncthreads();

    // A fragments (persistent): m16k16 from this warp's m-group
    const uint32_t sQh32 = smem_u32(sQh), sQl32 = smem_u32(sQl);
    const uint32_t aoff = ((uint32_t)(mg*16 + (lane & 15)) * PADC +
                           ((lane >> 4) & 1) * 8) * 2;
    uint32_t qfh[4], qfl[4];
    asm volatile("ldmatrix.sync.aligned.m8n8.x4.shared.b16 {%0,%1,%2,%3}, [%4];"
                 : "=r"(qfh[0]), "=r"(qfh[1]), "=r"(qfh[2]), "=r"(qfh[3])
                 : "r"(sQh32 + aoff));
    asm volatile("ldmatrix.sync.aligned.m8n8.x4.shared.b16 {%0,%1,%2,%3}, [%4];"
                 : "=r"(qfl[0]), "=r"(qfl[1]), "=r"(qfl[2]), "=r"(qfl[3])
                 : "r"(sQl32 + aoff));

    // per-lane top-8 for two rows: rowA = mg*16 + (lane>>2), rowB = rowA + 8
    const float INF = 3.4028235e38f;
    float    dA[8], dB[8]; uint32_t iA[8], iB[8];
    #pragma unroll
    for (int q = 0; q < 8; q++) { dA[q]=INF; dB[q]=INF; iA[q]=0; iB[q]=0; }

    const uint32_t cbh32 = smem_u32(sCh[ch]), cbl32 = smem_u32(sCl[ch]);
    const uint32_t boffB = (((uint32_t)((lane >> 4) & 1) * 8 + (lane & 7)) * PADC +
                            ((lane >> 3) & 1) * 8) * 2;

    for (int it = 0; it < NPTS / 256; it++) {
        __syncthreads();                       // prior consume done
        // ---- stage 2 candidate tiles (256 candidates) ----
        {
            const int cj = it*256 + t;
            const int which = t >> 7, nl = t & 127;
            float x = pts[cj*3+0], y = pts[cj*3+1], z = pts[cj*3+2];
            float s2 = x*x + y*y + z*z;
            __half hx, lx, hy, ly, hz, lz, hs, ls;
            h16_split(x, hx, lx);
            h16_split(y, hy, ly);
            h16_split(z, hz, lz);
            h16_split(s2, hs, ls);
            __half* ph = sCh[which] + nl * PADC;
            __half* pl = sCl[which] + nl * PADC;
            ph[0]=hx; ph[1]=hy; ph[2]=hz; ph[3]=hs;
            pl[0]=lx; pl[1]=ly; pl[2]=lz; pl[3]=ls;
            #pragma unroll
            for (int s = 4; s < 16; s++) {
                ph[s] = __ushort_as_half(0);
                pl[s] = __ushort_as_half(0);
            }
        }
        __syncthreads();

        const int cbase = it*256 + ch*TN;
        #pragma unroll
        for (int ntc = 0; ntc < 2; ntc++) {    // two n-chunks of 8 n-tiles
            uint32_t bh[16], bl[16];
            #pragma unroll
            for (int ntp = 0; ntp < 4; ntp++) {
                const uint32_t bo = boffB +
                    (uint32_t)(ntc*64 + ntp*16) * PADC * 2;
                asm volatile(
                    "ldmatrix.sync.aligned.m8n8.x4.shared.b16 {%0,%1,%2,%3}, [%4];"
                    : "=r"(bh[ntp*4]), "=r"(bh[ntp*4+1]),
                      "=r"(bh[ntp*4+2]), "=r"(bh[ntp*4+3])
                    : "r"(cbh32 + bo));
                asm volatile(
                    "ldmatrix.sync.aligned.m8n8.x4.shared.b16 {%0,%1,%2,%3}, [%4];"
                    : "=r"(bl[ntp*4]), "=r"(bl[ntp*4+1]),
                      "=r"(bl[ntp*4+2]), "=r"(bl[ntp*4+3])
                    : "r"(cbl32 + bo));
            }
            float d[8][4];
            #pragma unroll
            for (int nt = 0; nt < 8; nt++)
                { d[nt][0]=0.f; d[nt][1]=0.f; d[nt][2]=0.f; d[nt][3]=0.f; }
            #pragma unroll
            for (int nt = 0; nt < 8; nt++) {
                const int bi = (nt >> 1) * 4 + (nt & 1) * 2;
                asm volatile(
                    "mma.sync.aligned.m16n8k16.row.col.f32.f16.f16.f32 "
                    "{%0,%1,%2,%3}, {%4,%5,%6,%7}, {%8,%9}, {%0,%1,%2,%3};"
                    : "+f"(d[nt][0]), "+f"(d[nt][1]), "+f"(d[nt][2]), "+f"(d[nt][3])
                    : "r"(qfh[0]), "r"(qfh[1]), "r"(qfh[2]), "r"(qfh[3]),
                      "r"(bh[bi]), "r"(bh[bi+1]));
                asm volatile(
                    "mma.sync.aligned.m16n8k16.row.col.f32.f16.f16.f32 "
                    "{%0,%1,%2,%3}, {%4,%5,%6,%7}, {%8,%9}, {%0,%1,%2,%3};"
                    : "+f"(d[nt][0]), "+f"(d[nt][1]), "+f"(d[nt][2]), "+f"(d[nt][3])
                    : "r"(qfh[0]), "r"(qfh[1]), "r"(qfh[2]), "r"(qfh[3]),
                      "r"(bl[bi]), "r"(bl[bi+1]));
                asm volatile(
                    "mma.sync.aligned.m16n8k16.row.col.f32.f16.f16.f32 "
                    "{%0,%1,%2,%3}, {%4,%5,%6,%7}, {%8,%9}, {%0,%1,%2,%3};"
                    : "+f"(d[nt][0]), "+f"(d[nt][1]), "+f"(d[nt][2]), "+f"(d[nt][3])
                    : "r"(qfl[0]), "r"(qfl[1]), "r"(qfl[2]), "r"(qfl[3]),
                      "r"(bh[bi]), "r"(bh[bi+1]));
            }
            // ---- scan: min-tree + rare insert ----
            float pA[8], pB[8];
            #pragma unroll
            for (int nt = 0; nt < 8; nt++) {
                pA[nt] = fminf(d[nt][0], d[nt][1]);
                pB[nt] = fminf(d[nt][2], d[nt][3]);
            }
            float mA = fminf(fminf(fminf(pA[0],pA[1]), fminf(pA[2],pA[3])),
                             fminf(fminf(pA[4],pA[5]), fminf(pA[6],pA[7])));
            float mB = fminf(fminf(fminf(pB[0],pB[1]), fminf(pB[2],pB[3])),
                             fminf(fminf(pB[4],pB[5]), fminf(pB[6],pB[7])));
            if (mA < dA[7]) {
                #pragma unroll
                for (int nt = 0; nt < 8; nt++) {
                    #pragma unroll
                    for (int j = 0; j < 2; j++) {
                        float v = d[nt][j];
                        if (v < dA[7]) {
                            dA[7] = v;
                            iA[7] = (uint32_t)(cbase + (ntc*8 + nt)*8 +
                                               (lane & 3)*2 + j);
                            #pragma unroll
                            for (int s = 6; s >= 0; s--) {
                                bool sw = dA[s+1] < dA[s];
                                float    td = sw ? dA[s] : dA[s+1];
                                uint32_t ti = sw ? iA[s] : iA[s+1];
                                dA[s]   = sw ? dA[s+1] : dA[s];
                                iA[s]   = sw ? iA[s+1] : iA[s];
                                dA[s+1] = td; iA[s+1] = ti;
                            }
                        }
                    }
                }
            }
            if (mB < dB[7]) {
                #pragma unroll
                for (int nt = 0; nt < 8; nt++) {
                    #pragma unroll
                    for (int j = 0; j < 2; j++) {
                        float v = d[nt][2+j];
                        if (v < dB[7]) {
                            dB[7] = v;
                            iB[7] = (uint32_t)(cbase + (ntc*8 + nt)*8 +
                                               (lane & 3)*2 + j);
                            #pragma unroll
                            for (int s = 6; s >= 0; s--) {
                                bool sw = dB[s+1] < dB[s];
                                float    td = sw ? dB[s] : dB[s+1];
                                uint32_t ti = sw ? iB[s] : iB[s+1];
                                dB[s]   = sw ? dB[s+1] : dB[s];
                                iB[s]   = sw ? iB[s+1] : iB[s];
                                dB[s+1] = td; iB[s+1] = ti;
                            }
                        }
                    }
                }
            }
        }
    }

    // ---- lane-quad merge (4 lanes share each row), sorted output to smem ----
    {
        const int rowA = mg*16 + (lane >> 2);
        unsigned long long k[8];
        #pragma unroll
        for (int q = 0; q < 8; q++) {
            unsigned int ob = __float_as_uint(dA[q]);
            ob ^= ((unsigned int)((int)ob >> 31)) | 0x80000000u;
            k[q] = ((unsigned long long)ob << 32) | iA[q];
        }
        #pragma unroll
        for (int r = 0; r < 8; r++) {
            unsigned long long m = k[0];
            unsigned long long o = __shfl_xor_sync(0xFFFFFFFFu, m, 1);
            if (o < m) m = o;
            o = __shfl_xor_sync(0xFFFFFFFFu, m, 2);
            if (o < m) m = o;
            if (k[0] == m) {
                #pragma unroll
                for (int s = 0; s < 7; s++) k[s] = k[s+1];
                k[7] = 0xFFFFFFFFFFFFFFFFULL;
            }
            if ((lane & 3) == 0) sMrg[ch][rowA][r] = m;
        }
        const int rowB = rowA + 8;
        #pragma unroll
        for (int q = 0; q < 8; q++) {
            unsigned int ob = __float_as_uint(dB[q]);
            ob ^= ((unsigned int)((int)ob >> 31)) | 0x80000000u;
            k[q] = ((unsigned long long)ob << 32) | iB[q];
        }
        #pragma unroll
        for (int r = 0; r < 8; r++) {
            unsigned long long m = k[0];
            unsigned long long o = __shfl_xor_sync(0xFFFFFFFFu, m, 1);
            if (o < m) m = o;
            o = __shfl_xor_sync(0xFFFFFFFFu, m, 2);
            if (o < m) m = o;
            if (k[0] == m) {
                #pragma unroll
                for (int s = 0; s < 7; s++) k[s] = k[s+1];
                k[7] = 0xFFFFFFFFFFFFFFFFULL;
            }
            if ((lane & 3) == 0) sMrg[ch][rowB][r] = m;
        }
    }
    __syncthreads();

    // ---- final two-pointer merge of the two candidate-half lists ----
    if (t < QB) {
        int i0 = 0, i1 = 0;
        #pragma unroll
        for (int r = 0; r < 8; r++) {
            unsigned long long a = sMrg[0][t][i0];
            unsigned long long b = sMrg[1][t][i1];
            if (a <= b) { g_knn[(qi0 + t)*KNN + r] = (int)(a & 0xFFFFFFFFu); i0++; }
            else        { g_knn[(qi0 + t)*KNN + r] = (int)(b & 0xFFFFFFFFu); i1++; }
        }
    }
}

// ---------------- Kernel 2: EdgeConv1, layer2 on tensor cores ---------------
#define PADK2 72
__global__ __launch_bounds__(256) void conv1_kernel(
    const float* __restrict__ pts,
    const float* __restrict__ W1, const float* __restrict__ b1,
    const float* __restrict__ b2)
{
    __shared__ float  se[16][8][6];
    __shared__ __half sE[128 * PADK2];
    __shared__ __half sW[128 * PADK2];
    const int t    = threadIdx.x;
    const int lane = t & 31;
    const int w    = t >> 5;
    const int p0   = blockIdx.x * 16;

    {
        #pragma unroll
        for (int g = 0; g < 4; g++) {
            int idx = t + g*256;
            int row = idx >> 3, part = idx & 7;
            uint4 v = *((const uint4*)(g_w2h + row*64) + part);
            *((uint4*)(sW + row*PADK2) + part) = v;
        }
    }
    if (t < 128) {
        int p = t >> 3, e = t & 7;
        int i = p0 + p;
        int j = g_knn[i*KNN + e];
        float xi0 = pts[i*3+0], xi1 = pts[i*3+1], xi2 = pts[i*3+2];
        float xj0 = pts[j*3+0], xj1 = pts[j*3+1], xj2 = pts[j*3+2];
        se[p][e][0] = xi0; se[p][e][1] = xi1; se[p][e][2] = xi2;
        se[p][e][3] = xj0 - xi0; se[p][e][4] = xj1 - xi1; se[p][e][5] = xj2 - xi2;
    }
    __syncthreads();

    #pragma unroll
    for (int r = 0; r < 32; r++) {
        int id = t + r*256;
        int e = id & 7, p = (id >> 3) & 15, u = id >> 7;
        float acc = b1[u];
        #pragma unroll
        for (int f = 0; f < 6; f++) acc += se[p][e][f] * W1[f*64 + u];
        sE[(p*8 + e) * PADK2 + u] = __float2half_rn(fmaxf(acc, 0.0f));
    }
    __syncthreads();

    const int mw = w & 1, nw = w >> 1;
    const int m0 = mw * 64;
    const int n0 = nw * 32;

    const uint32_t sE32 = smem_u32(sE), sW32 = smem_u32(sW);
    const uint32_t aoff = ((uint32_t)(m0 + (lane & 15)) * PADK2 +
                           ((lane >> 4) & 1) * 8) * 2;
    const uint32_t boff = ((uint32_t)(n0 + ((lane >> 4) & 1) * 8 + (lane & 7)) * PADK2 +
                           ((lane >> 3) & 1) * 8) * 2;

    float d[4][4][4];
    #pragma unroll
    for (int mt = 0; mt < 4; mt++)
        #pragma unroll
        for (int nt = 0; nt < 4; nt++)
            { d[mt][nt][0]=0.f; d[mt][nt][1]=0.f; d[mt][nt][2]=0.f; d[mt][nt][3]=0.f; }

    #pragma unroll
    for (int k16 = 0; k16 < 4; k16++) {
        const uint32_t kb = k16 * 32;
        uint32_t a[4][4];
        #pragma unroll
        for (int mt = 0; mt < 4; mt++) {
            asm volatile(
                "ldmatrix.sync.aligned.m8n8.x4.shared.b16 {%0,%1,%2,%3}, [%4];"
                : "=r"(a[mt][0]), "=r"(a[mt][1]), "=r"(a[mt][2]), "=r"(a[mt][3])
                : "r"(sE32 + aoff + (uint32_t)mt * (16 * PADK2 * 2) + kb));
        }
        uint32_t b[8];
        #pragma unroll
        for (int ntp = 0; ntp < 2; ntp++) {
            asm volatile(
                "ldmatrix.sync.aligned.m8n8.x4.shared.b16 {%0,%1,%2,%3}, [%4];"
                : "=r"(b[ntp*4]), "=r"(b[ntp*4+1]), "=r"(b[ntp*4+2]), "=r"(b[ntp*4+3])
                : "r"(sW32 + boff + (uint32_t)ntp * (16 * PADK2 * 2) + kb));
        }
        #pragma unroll
        for (int mt = 0; mt < 4; mt++) {
            #pragma unroll
            for (int nt = 0; nt < 4; nt++) {
                const int bi = (nt >> 1) * 4 + (nt & 1) * 2;
                asm volatile(
                    "mma.sync.aligned.m16n8k16.row.col.f32.f16.f16.f32 "
                    "{%0,%1,%2,%3}, {%4,%5,%6,%7}, {%8,%9}, {%0,%1,%2,%3};"
                    : "+f"(d[mt][nt][0]), "+f"(d[mt][nt][1]),
                      "+f"(d[mt][nt][2]), "+f"(d[mt][nt][3])
                    : "r"(a[mt][0]), "r"(a[mt][1]), "r"(a[mt][2]), "r"(a[mt][3]),
                      "r"(b[bi]), "r"(b[bi+1]));
            }
        }
    }

    #pragma unroll
    for (int mt = 0; mt < 4; mt++) {
        #pragma unroll
        for (int nt = 0; nt < 4; nt++) {
            float v0 = d[mt][nt][0], v1 = d[mt][nt][1];
            float v2 = d[mt][nt][2], v3 = d[mt][nt][3];
            #pragma unroll
            for (int off = 4; off <= 16; off <<= 1) {
                v0 = fmaxf(v0, __shfl_xor_sync(0xFFFFFFFFu, v0, off));
                v1 = fmaxf(v1, __shfl_xor_sync(0xFFFFFFFFu, v1, off));
                v2 = fmaxf(v2, __shfl_xor_sync(0xFFFFFFFFu, v2, off));
                v3 = fmaxf(v3, __shfl_xor_sync(0xFFFFFFFFu, v3, off));
            }
            if (lane < 4) {
                const int c = n0 + nt * 8 + lane * 2;
                const float2 bb = *(const float2*)(b2 + c);
                const int pA = p0 + mw * 8 + mt * 2;
                __half2 hA = __floats2half2_rn(fmaxf(v0 + bb.x, 0.0f),
                                               fmaxf(v1 + bb.y, 0.0f));
                __half2 hB = __floats2half2_rn(fmaxf(v2 + bb.x, 0.0f),
                                               fmaxf(v3 + bb.y, 0.0f));
                *(uint32_t*)(g_x1h + (size_t)(pA    ) * 128 + c) = *(uint32_t*)&hA;
                *(uint32_t*)(g_x1h + (size_t)(pA + 1) * 128 + c) = *(uint32_t*)&hB;
            }
        }
    }
}

// ---------------- Kernel 3: pre2 as fp16 GEMM -------------------------------
#define PADK 136
#define P_A_ELEMS (64  * PADK)
#define P_B_ELEMS (256 * PADK)
#define PRE2_SMEM ((P_A_ELEMS + P_B_ELEMS) * 2)

__global__ __launch_bounds__(256, 2) void pre2t_kernel(const float* __restrict__ b3)
{
    extern __shared__ __align__(16) char smem[];
    __half* sA = (__half*)smem;
    __half* sB = sA + P_A_ELEMS;

    const int t    = threadIdx.x;
    const int lane = t & 31;
    const int w    = t >> 5;
    const int i0   = blockIdx.x * 64;

    {
        const int r = t >> 2, q = t & 3;
        #pragma unroll
        for (int g = 0; g < 4; g++) {
            uint4 v = *((const uint4*)(g_x1h + (size_t)(i0 + r) * 128) + q*4 + g);
            *((uint4*)(sA + r * PADK) + q*4 + g) = v;
        }
    }
    {
        const uint4* s4 = (const uint4*)(g_w3h + (size_t)t * 128);
        uint4* d4 = (uint4*)(sB + t * PADK);
        #pragma unroll
        for (int kg = 0; kg < 16; kg++) d4[kg] = s4[kg];
    }
    __syncthreads();

    const int mw  = w & 1;
    const int nwp = w >> 1;
    const int m0  = mw * 32;
    const int n0  = nwp * 64;

    const uint32_t sA32 = smem_u32(sA), sB32 = smem_u32(sB);
    const uint32_t aoff = ((uint32_t)(m0 + (lane & 15)) * PADK +
                           ((lane >> 4) & 1) * 8) * 2;
    const uint32_t boff = ((uint32_t)(n0 + ((lane >> 4) & 1) * 8 + (lane & 7)) * PADK +
                           ((lane >> 3) & 1) * 8) * 2;

    float d[2][8][4];
    #pragma unroll
    for (int mt = 0; mt < 2; mt++)
        #pragma unroll
        for (int nt = 0; nt < 8; nt++)
            { d[mt][nt][0]=0.f; d[mt][nt][1]=0.f; d[mt][nt][2]=0.f; d[mt][nt][3]=0.f; }

    #pragma unroll
    for (int k16 = 0; k16 < 8; k16++) {
        const uint32_t kb = k16 * 32;
        uint32_t a[2][4];
        #pragma unroll
        for (int mt = 0; mt < 2; mt++) {
            asm volatile(
                "ldmatrix.sync.aligned.m8n8.x4.shared.b16 {%0,%1,%2,%3}, [%4];"
                : "=r"(a[mt][0]), "=r"(a[mt][1]), "=r"(a[mt][2]), "=r"(a[mt][3])
                : "r"(sA32 + aoff + (uint32_t)mt * (16 * PADK * 2) + kb));
        }
        uint32_t b[16];
        #pragma unroll
        for (int ntp = 0; ntp < 4; ntp++) {
            asm volatile(
                "ldmatrix.sync.aligned.m8n8.x4.shared.b16 {%0,%1,%2,%3}, [%4];"
                : "=r"(b[ntp*4]), "=r"(b[ntp*4+1]), "=r"(b[ntp*4+2]), "=r"(b[ntp*4+3])
                : "r"(sB32 + boff + (uint32_t)ntp * (16 * PADK * 2) + kb));
        }
        #pragma unroll
        for (int mt = 0; mt < 2; mt++) {
            #pragma unroll
            for (int nt = 0; nt < 8; nt++) {
                const int bi = (nt >> 1) * 4 + (nt & 1) * 2;
                asm volatile(
                    "mma.sync.aligned.m16n8k16.row.col.f32.f16.f16.f32 "
                    "{%0,%1,%2,%3}, {%4,%5,%6,%7}, {%8,%9}, {%0,%1,%2,%3};"
                    : "+f"(d[mt][nt][0]), "+f"(d[mt][nt][1]),
                      "+f"(d[mt][nt][2]), "+f"(d[mt][nt][3])
                    : "r"(a[mt][0]), "r"(a[mt][1]), "r"(a[mt][2]), "r"(a[mt][3]),
                      "r"(b[bi]), "r"(b[bi+1]));
            }
        }
    }

    #pragma unroll
    for (int mt = 0; mt < 2; mt++) {
        const int r0 = m0 + mt*16 + (lane >> 2);
        const int iAr = i0 + r0, iBr = i0 + r0 + 8;
        #pragma unroll
        for (int nt = 0; nt < 8; nt++) {
            const int c = n0 + nt * 8 + (lane & 3) * 2;
            if (c < 128) {
                const float2 bb = *(const float2*)(b3 + c);
                float2 o0; o0.x = d[mt][nt][0] + bb.x; o0.y = d[mt][nt][1] + bb.y;
                float2 o1; o1.x = d[mt][nt][2] + bb.x; o1.y = d[mt][nt][3] + bb.y;
                *(float2*)(g_A + (size_t)iAr * 128 + c) = o0;
                *(float2*)(g_A + (size_t)iBr * 128 + c) = o1;
            } else {
                float2 o0; o0.x = d[mt][nt][0]; o0.y = d[mt][nt][1];
                float2 o1; o1.x = d[mt][nt][2]; o1.y = d[mt][nt][3];
                *(float2*)(g_B + (size_t)iAr * 128 + (c - 128)) = o0;
                *(float2*)(g_B + (size_t)iBr * 128 + (c - 128)) = o1;
            }
        }
    }
}

// ---------------- Kernel 4: EdgeConv2 via mma.sync fp16 ---------------------
#define A_ELEMS (64  * PADK)
#define B_ELEMS (256 * PADK)
#define CONV2_SMEM ((A_ELEMS + B_ELEMS) * 2)

__global__ __launch_bounds__(256, 2) void conv2m_kernel(
    const float* __restrict__ b4, float* __restrict__ out)
{
    extern __shared__ __align__(16) char smem[];
    __half* sA = (__half*)smem;
    __half* sB = sA + A_ELEMS;

    const int t    = threadIdx.x;
    const int lane = t & 31;
    const int w    = t >> 5;
    const int p0   = blockIdx.x * 8;

    {
        const uint4* s4 = (const uint4*)(g_w4h + (size_t)t * 128);
        uint4* d4 = (uint4*)(sB + t * PADK);
        #pragma unroll
        for (int kg = 0; kg < 16; kg++) d4[kg] = s4[kg];
    }
    {
        const int r = t >> 2, q = t & 3;
        const int i = p0 + (r >> 3);
        const int j = g_knn[i * KNN + (r & 7)];
        const float4* pa = (const float4*)(g_A + (size_t)i * 128 + q * 32);
        const float4* pb = (const float4*)(g_B + (size_t)j * 128 + q * 32);
        uint2* dh = (uint2*)(sA + r * PADK + q * 32);
        #pragma unroll
        for (int kg = 0; kg < 8; kg++) {
            float4 a = pa[kg];
            float4 b = pb[kg];
            float h0 = fmaxf(a.x + b.x, 0.0f);
            float h1 = fmaxf(a.y + b.y, 0.0f);
            float h2 = fmaxf(a.z + b.z, 0.0f);
            float h3 = fmaxf(a.w + b.w, 0.0f);
            __half2 lo2 = __float22half2_rn(make_float2(h0, h1));
            __half2 hi2 = __float22half2_rn(make_float2(h2, h3));
            uint2 v;
            v.x = *(uint32_t*)&lo2;
            v.y = *(uint32_t*)&hi2;
            dh[kg] = v;
        }
    }
    __syncthreads();

    const int mw  = w & 1;
    const int nwp = w >> 1;
    const int m0  = mw * 32;
    const int n0  = nwp * 64;

    const uint32_t sA32 = smem_u32(sA), sB32 = smem_u32(sB);
    const uint32_t aoff = ((uint32_t)(m0 + (lane & 15)) * PADK +
                           ((lane >> 4) & 1) * 8) * 2;
    const uint32_t boff = ((uint32_t)(n0 + ((lane >> 4) & 1) * 8 + (lane & 7)) * PADK +
                           ((lane >> 3) & 1) * 8) * 2;

    float d[2][8][4];
    #pragma unroll
    for (int mt = 0; mt < 2; mt++)
        #pragma unroll
        for (int nt = 0; nt < 8; nt++)
            { d[mt][nt][0]=0.f; d[mt][nt][1]=0.f; d[mt][nt][2]=0.f; d[mt][nt][3]=0.f; }

    #pragma unroll
    for (int k16 = 0; k16 < 8; k16++) {
        const uint32_t kb = k16 * 32;
        uint32_t a[2][4];
        #pragma unroll
        for (int mt = 0; mt < 2; mt++) {
            asm volatile(
                "ldmatrix.sync.aligned.m8n8.x4.shared.b16 {%0,%1,%2,%3}, [%4];"
                : "=r"(a[mt][0]), "=r"(a[mt][1]), "=r"(a[mt][2]), "=r"(a[mt][3])
                : "r"(sA32 + aoff + (uint32_t)mt * (16 * PADK * 2) + kb));
        }
        uint32_t b[16];
        #pragma unroll
        for (int ntp = 0; ntp < 4; ntp++) {
            asm volatile(
                "ldmatrix.sync.aligned.m8n8.x4.shared.b16 {%0,%1,%2,%3}, [%4];"
                : "=r"(b[ntp*4]), "=r"(b[ntp*4+1]), "=r"(b[ntp*4+2]), "=r"(b[ntp*4+3])
                : "r"(sB32 + boff + (uint32_t)ntp * (16 * PADK * 2) + kb));
        }
        #pragma unroll
        for (int mt = 0; mt < 2; mt++) {
            #pragma unroll
            for (int nt = 0; nt < 8; nt++) {
                const int bi = (nt >> 1) * 4 + (nt & 1) * 2;
                asm volatile(
                    "mma.sync.aligned.m16n8k16.row.col.f32.f16.f16.f32 "
                    "{%0,%1,%2,%3}, {%4,%5,%6,%7}, {%8,%9}, {%0,%1,%2,%3};"
                    : "+f"(d[mt][nt][0]), "+f"(d[mt][nt][1]),
                      "+f"(d[mt][nt][2]), "+f"(d[mt][nt][3])
                    : "r"(a[mt][0]), "r"(a[mt][1]), "r"(a[mt][2]), "r"(a[mt][3]),
                      "r"(b[bi]), "r"(b[bi+1]));
            }
        }
    }

    #pragma unroll
    for (int mt = 0; mt < 2; mt++) {
        #pragma unroll
        for (int nt = 0; nt < 8; nt++) {
            float v0 = d[mt][nt][0], v1 = d[mt][nt][1];
            float v2 = d[mt][nt][2], v3 = d[mt][nt][3];
            #pragma unroll
            for (int off = 4; off <= 16; off <<= 1) {
                v0 = fmaxf(v0, __shfl_xor_sync(0xFFFFFFFFu, v0, off));
                v1 = fmaxf(v1, __shfl_xor_sync(0xFFFFFFFFu, v1, off));
                v2 = fmaxf(v2, __shfl_xor_sync(0xFFFFFFFFu, v2, off));
                v3 = fmaxf(v3, __shfl_xor_sync(0xFFFFFFFFu, v3, off));
            }
            if (lane < 4) {
                const int c = n0 + nt * 8 + lane * 2;
                const float2 bb = *(const float2*)(b4 + c);
                const int pbase = p0 + mw * 4 + mt * 2;
                float2 o0; o0.x = v0 + bb.x; o0.y = v1 + bb.y;
                float2 o1; o1.x = v2 + bb.x; o1.y = v3 + bb.y;
                *(float2*)(out + (size_t)(pbase    ) * 256 + c) = o0;
                *(float2*)(out + (size_t)(pbase + 1) * 256 + c) = o1;
            }
        }
    }
}

// ---------------- launch -----------------------------------------------------
extern "C" void kernel_launch(void* const* d_in, const int* in_sizes, int n_in,
                              void* d_out, int out_size) {
    const float* pts = (const float*)d_in[0];
    const float* W1  = (const float*)d_in[1];
    const float* b1  = (const float*)d_in[2];
    const float* W2  = (const float*)d_in[3];
    const float* b2  = (const float*)d_in[4];
    const float* W3  = (const float*)d_in[5];
    const float* b3  = (const float*)d_in[6];
    const float* W4  = (const float*)d_in[7];
    const float* b4  = (const float*)d_in[8];
    float* out = (float*)d_out;

    cudaFuncSetAttribute(pre2t_kernel,
                         cudaFuncAttributeMaxDynamicSharedMemorySize, PRE2_SMEM);
    cudaFuncSetAttribute(conv2m_kernel,
                         cudaFuncAttributeMaxDynamicSharedMemorySize, CONV2_SMEM);

    knn_kernel   <<<NPTS/QB, 256>>>(pts, W2, W3, W4);
    conv1_kernel <<<NPTS/16, 256>>>(pts, W1, b1, b2);
    pre2t_kernel <<<NPTS/64, 256, PRE2_SMEM>>>(b3);
    conv2m_kernel<<<NPTS/8, 256, CONV2_SMEM>>>(b4, out);
}

// round 12
// speedup vs baseline: 1.4664x; 1.4664x over previous
#include <cuda_runtime.h>
#include <cuda_fp16.h>
#include <cstdint>

#define NPTS 8192
#define KNN  8

// ---------------- scratch (device globals: no allocations allowed) ----------
__device__ int   g_knn[NPTS * KNN];
__device__ unsigned short g_x1h[NPTS * 128];  // edgeconv1 output fp16 [i][k]
__device__ unsigned short g_Ah[NPTS * 128];   // fp16: x1 @ (W3a-W3b) + b3
__device__ unsigned short g_Bh[NPTS * 128];   // fp16: x1 @ W3b
__device__ unsigned short g_w2h[128 * 64];    // W2^T fp16 [c][u]
__device__ unsigned short g_w3h[256 * 128];   // [Wd^T ; Wb^T] fp16 [n][k]
__device__ unsigned short g_w4h[256 * 128];   // W4^T fp16 [c][k]

// ---------------- helpers ----------------------------------------------------
__device__ __forceinline__ uint32_t smem_u32(const void* p) {
    uint32_t a;
    asm("{ .reg .u64 t; cvta.to.shared.u64 t, %1; cvt.u32.u64 %0, t; }"
        : "=r"(a) : "l"(p));
    return a;
}

// ---------------- Kernel 1: KNN (scalar batch-8 gated; R10 proven) ----------
__global__ __launch_bounds__(256) void knn_kernel(
    const float* __restrict__ pts,
    const float* __restrict__ W2, const float* __restrict__ W3,
    const float* __restrict__ W4)
{
    // weight conversion prologue (blocks 0..319, no syncs inside)
    {
        const int b = blockIdx.x, t = threadIdx.x;
        if (b < 64) {
            if (t < 128) {
                g_w2h[t*64 + b] = __half_as_ushort(__float2half_rn(W2[b*128 + t]));
            }
        } else if (b < 192) {
            if (t < 128) {
                int k = b - 64;
                float wa = W3[k*128 + t];
                float wb = W3[(k+128)*128 + t];
                g_w3h[t*128 + k]        = __half_as_ushort(__float2half_rn(wa - wb));
                g_w3h[(128+t)*128 + k]  = __half_as_ushort(__float2half_rn(wb));
            }
        } else if (b < 320) {
            int k = b - 192;
            g_w4h[t*128 + k] = __half_as_ushort(__float2half_rn(W4[k*256 + t]));
        }
    }

    const int TS = 2048;
    __shared__ float4 sp[TS];
    const int lane = threadIdx.x & 31;
    const int warp = threadIdx.x >> 5;
    const int qi = blockIdx.x * 8 + warp;

    const float qx = pts[qi*3+0], qy = pts[qi*3+1], qz = pts[qi*3+2];
    const float ax = -2.0f*qx, ay = -2.0f*qy, az = -2.0f*qz;

    const float INF = 3.4028235e38f;
    float    ld[8]; unsigned int li[8];
    #pragma unroll
    for (int q = 0; q < 8; q++) { ld[q] = INF; li[q] = 0xFFFFFFFFu; }

    for (int base = 0; base < NPTS; base += TS) {
        __syncthreads();
        for (int t = threadIdx.x; t < TS; t += 256) {
            float x = pts[(base+t)*3+0];
            float y = pts[(base+t)*3+1];
            float z = pts[(base+t)*3+2];
            sp[t] = make_float4(x, y, z, x*x + y*y + z*z);
        }
        __syncthreads();

        for (int jb = 0; jb < TS; jb += 256) {
            float dd[8];
            #pragma unroll
            for (int q = 0; q < 8; q++) {
                float4 p = sp[jb + q*32 + lane];
                dd[q] = fmaf(ax, p.x, fmaf(ay, p.y, fmaf(az, p.z, p.w)));
            }
            float m01 = fminf(dd[0], dd[1]), m23 = fminf(dd[2], dd[3]);
            float m45 = fminf(dd[4], dd[5]), m67 = fminf(dd[6], dd[7]);
            float mn = fminf(fminf(m01, m23), fminf(m45, m67));
            if (mn < ld[7]) {
                #pragma unroll
                for (int q = 0; q < 8; q++) {
                    float x = dd[q];
                    if (x < ld[7]) {
                        unsigned int ix = (unsigned int)(base + jb + q*32 + lane);
                        ld[7] = x; li[7] = ix;
                        #pragma unroll
                        for (int s = 6; s >= 0; s--) {
                            bool sw = ld[s+1] < ld[s];
                            float  td = sw ? ld[s] : ld[s+1];
                            unsigned int ti = sw ? li[s] : li[s+1];
                            ld[s]   = sw ? ld[s+1] : ld[s];
                            li[s]   = sw ? li[s+1] : li[s];
                            ld[s+1] = td; li[s+1] = ti;
                        }
                    }
                }
            }
        }
    }

    unsigned long long k[8];
    #pragma unroll
    for (int q = 0; q < 8; q++) {
        unsigned int ob = __float_as_uint(ld[q]);
        ob ^= ((unsigned int)((int)ob >> 31)) | 0x80000000u;
        k[q] = ((unsigned long long)ob << 32) | li[q];
    }
    #pragma unroll
    for (int r = 0; r < KNN; r++) {
        unsigned long long m = k[0];
        #pragma unroll
        for (int off = 16; off; off >>= 1) {
            unsigned long long o = __shfl_xor_sync(0xFFFFFFFFu, m, off);
            if (o < m) m = o;
        }
        if (k[0] == m) {
            #pragma unroll
            for (int s = 0; s < 7; s++) k[s] = k[s+1];
            k[7] = 0xFFFFFFFFFFFFFFFFULL;
        }
        if (lane == 0) g_knn[qi*KNN + r] = (int)(m & 0xFFFFFFFFu);
    }
}

// ---------------- Kernel 2: EdgeConv1, layer2 on tensor cores ---------------
#define PADK2 72
__global__ __launch_bounds__(256) void conv1_kernel(
    const float* __restrict__ pts,
    const float* __restrict__ W1, const float* __restrict__ b1,
    const float* __restrict__ b2)
{
    __shared__ float  se[16][8][6];
    __shared__ __half sE[128 * PADK2];
    __shared__ __half sW[128 * PADK2];
    const int t    = threadIdx.x;
    const int lane = t & 31;
    const int w    = t >> 5;
    const int p0   = blockIdx.x * 16;

    {
        #pragma unroll
        for (int g = 0; g < 4; g++) {
            int idx = t + g*256;
            int row = idx >> 3, part = idx & 7;
            uint4 v = *((const uint4*)(g_w2h + row*64) + part);
            *((uint4*)(sW + row*PADK2) + part) = v;
        }
    }
    if (t < 128) {
        int p = t >> 3, e = t & 7;
        int i = p0 + p;
        int j = g_knn[i*KNN + e];
        float xi0 = pts[i*3+0], xi1 = pts[i*3+1], xi2 = pts[i*3+2];
        float xj0 = pts[j*3+0], xj1 = pts[j*3+1], xj2 = pts[j*3+2];
        se[p][e][0] = xi0; se[p][e][1] = xi1; se[p][e][2] = xi2;
        se[p][e][3] = xj0 - xi0; se[p][e][4] = xj1 - xi1; se[p][e][5] = xj2 - xi2;
    }
    __syncthreads();

    #pragma unroll
    for (int r = 0; r < 32; r++) {
        int id = t + r*256;
        int e = id & 7, p = (id >> 3) & 15, u = id >> 7;
        float acc = b1[u];
        #pragma unroll
        for (int f = 0; f < 6; f++) acc += se[p][e][f] * W1[f*64 + u];
        sE[(p*8 + e) * PADK2 + u] = __float2half_rn(fmaxf(acc, 0.0f));
    }
    __syncthreads();

    const int mw = w & 1, nw = w >> 1;
    const int m0 = mw * 64;
    const int n0 = nw * 32;

    const uint32_t sE32 = smem_u32(sE), sW32 = smem_u32(sW);
    const uint32_t aoff = ((uint32_t)(m0 + (lane & 15)) * PADK2 +
                           ((lane >> 4) & 1) * 8) * 2;
    const uint32_t boff = ((uint32_t)(n0 + ((lane >> 4) & 1) * 8 + (lane & 7)) * PADK2 +
                           ((lane >> 3) & 1) * 8) * 2;

    float d[4][4][4];
    #pragma unroll
    for (int mt = 0; mt < 4; mt++)
        #pragma unroll
        for (int nt = 0; nt < 4; nt++)
            { d[mt][nt][0]=0.f; d[mt][nt][1]=0.f; d[mt][nt][2]=0.f; d[mt][nt][3]=0.f; }

    #pragma unroll
    for (int k16 = 0; k16 < 4; k16++) {
        const uint32_t kb = k16 * 32;
        uint32_t a[4][4];
        #pragma unroll
        for (int mt = 0; mt < 4; mt++) {
            asm volatile(
                "ldmatrix.sync.aligned.m8n8.x4.shared.b16 {%0,%1,%2,%3}, [%4];"
                : "=r"(a[mt][0]), "=r"(a[mt][1]), "=r"(a[mt][2]), "=r"(a[mt][3])
                : "r"(sE32 + aoff + (uint32_t)mt * (16 * PADK2 * 2) + kb));
        }
        uint32_t b[8];
        #pragma unroll
        for (int ntp = 0; ntp < 2; ntp++) {
            asm volatile(
                "ldmatrix.sync.aligned.m8n8.x4.shared.b16 {%0,%1,%2,%3}, [%4];"
                : "=r"(b[ntp*4]), "=r"(b[ntp*4+1]), "=r"(b[ntp*4+2]), "=r"(b[ntp*4+3])
                : "r"(sW32 + boff + (uint32_t)ntp * (16 * PADK2 * 2) + kb));
        }
        #pragma unroll
        for (int mt = 0; mt < 4; mt++) {
            #pragma unroll
            for (int nt = 0; nt < 4; nt++) {
                const int bi = (nt >> 1) * 4 + (nt & 1) * 2;
                asm volatile(
                    "mma.sync.aligned.m16n8k16.row.col.f32.f16.f16.f32 "
                    "{%0,%1,%2,%3}, {%4,%5,%6,%7}, {%8,%9}, {%0,%1,%2,%3};"
                    : "+f"(d[mt][nt][0]), "+f"(d[mt][nt][1]),
                      "+f"(d[mt][nt][2]), "+f"(d[mt][nt][3])
                    : "r"(a[mt][0]), "r"(a[mt][1]), "r"(a[mt][2]), "r"(a[mt][3]),
                      "r"(b[bi]), "r"(b[bi+1]));
            }
        }
    }

    #pragma unroll
    for (int mt = 0; mt < 4; mt++) {
        #pragma unroll
        for (int nt = 0; nt < 4; nt++) {
            float v0 = d[mt][nt][0], v1 = d[mt][nt][1];
            float v2 = d[mt][nt][2], v3 = d[mt][nt][3];
            #pragma unroll
            for (int off = 4; off <= 16; off <<= 1) {
                v0 = fmaxf(v0, __shfl_xor_sync(0xFFFFFFFFu, v0, off));
                v1 = fmaxf(v1, __shfl_xor_sync(0xFFFFFFFFu, v1, off));
                v2 = fmaxf(v2, __shfl_xor_sync(0xFFFFFFFFu, v2, off));
                v3 = fmaxf(v3, __shfl_xor_sync(0xFFFFFFFFu, v3, off));
            }
            if (lane < 4) {
                const int c = n0 + nt * 8 + lane * 2;
                const float2 bb = *(const float2*)(b2 + c);
                const int pA = p0 + mw * 8 + mt * 2;
                __half2 hA = __floats2half2_rn(fmaxf(v0 + bb.x, 0.0f),
                                               fmaxf(v1 + bb.y, 0.0f));
                __half2 hB = __floats2half2_rn(fmaxf(v2 + bb.x, 0.0f),
                                               fmaxf(v3 + bb.y, 0.0f));
                *(uint32_t*)(g_x1h + (size_t)(pA    ) * 128 + c) = *(uint32_t*)&hA;
                *(uint32_t*)(g_x1h + (size_t)(pA + 1) * 128 + c) = *(uint32_t*)&hB;
            }
        }
    }
}

// ---------------- Kernel 3: pre2 as fp16 GEMM, fp16 outputs -----------------
#define PADK 136
#define P_A_ELEMS (64  * PADK)
#define P_B_ELEMS (256 * PADK)
#define PRE2_SMEM ((P_A_ELEMS + P_B_ELEMS) * 2)

__global__ __launch_bounds__(256, 2) void pre2t_kernel(const float* __restrict__ b3)
{
    extern __shared__ __align__(16) char smem[];
    __half* sA = (__half*)smem;
    __half* sB = sA + P_A_ELEMS;

    const int t    = threadIdx.x;
    const int lane = t & 31;
    const int w    = t >> 5;
    const int i0   = blockIdx.x * 64;

    {
        const int r = t >> 2, q = t & 3;
        #pragma unroll
        for (int g = 0; g < 4; g++) {
            uint4 v = *((const uint4*)(g_x1h + (size_t)(i0 + r) * 128) + q*4 + g);
            *((uint4*)(sA + r * PADK) + q*4 + g) = v;
        }
    }
    {
        const uint4* s4 = (const uint4*)(g_w3h + (size_t)t * 128);
        uint4* d4 = (uint4*)(sB + t * PADK);
        #pragma unroll
        for (int kg = 0; kg < 16; kg++) d4[kg] = s4[kg];
    }
    __syncthreads();

    const int mw  = w & 1;
    const int nwp = w >> 1;
    const int m0  = mw * 32;
    const int n0  = nwp * 64;

    const uint32_t sA32 = smem_u32(sA), sB32 = smem_u32(sB);
    const uint32_t aoff = ((uint32_t)(m0 + (lane & 15)) * PADK +
                           ((lane >> 4) & 1) * 8) * 2;
    const uint32_t boff = ((uint32_t)(n0 + ((lane >> 4) & 1) * 8 + (lane & 7)) * PADK +
                           ((lane >> 3) & 1) * 8) * 2;

    float d[2][8][4];
    #pragma unroll
    for (int mt = 0; mt < 2; mt++)
        #pragma unroll
        for (int nt = 0; nt < 8; nt++)
            { d[mt][nt][0]=0.f; d[mt][nt][1]=0.f; d[mt][nt][2]=0.f; d[mt][nt][3]=0.f; }

    #pragma unroll
    for (int k16 = 0; k16 < 8; k16++) {
        const uint32_t kb = k16 * 32;
        uint32_t a[2][4];
        #pragma unroll
        for (int mt = 0; mt < 2; mt++) {
            asm volatile(
                "ldmatrix.sync.aligned.m8n8.x4.shared.b16 {%0,%1,%2,%3}, [%4];"
                : "=r"(a[mt][0]), "=r"(a[mt][1]), "=r"(a[mt][2]), "=r"(a[mt][3])
                : "r"(sA32 + aoff + (uint32_t)mt * (16 * PADK * 2) + kb));
        }
        uint32_t b[16];
        #pragma unroll
        for (int ntp = 0; ntp < 4; ntp++) {
            asm volatile(
                "ldmatrix.sync.aligned.m8n8.x4.shared.b16 {%0,%1,%2,%3}, [%4];"
                : "=r"(b[ntp*4]), "=r"(b[ntp*4+1]), "=r"(b[ntp*4+2]), "=r"(b[ntp*4+3])
                : "r"(sB32 + boff + (uint32_t)ntp * (16 * PADK * 2) + kb));
        }
        #pragma unroll
        for (int mt = 0; mt < 2; mt++) {
            #pragma unroll
            for (int nt = 0; nt < 8; nt++) {
                const int bi = (nt >> 1) * 4 + (nt & 1) * 2;
                asm volatile(
                    "mma.sync.aligned.m16n8k16.row.col.f32.f16.f16.f32 "
                    "{%0,%1,%2,%3}, {%4,%5,%6,%7}, {%8,%9}, {%0,%1,%2,%3};"
                    : "+f"(d[mt][nt][0]), "+f"(d[mt][nt][1]),
                      "+f"(d[mt][nt][2]), "+f"(d[mt][nt][3])
                    : "r"(a[mt][0]), "r"(a[mt][1]), "r"(a[mt][2]), "r"(a[mt][3]),
                      "r"(b[bi]), "r"(b[bi+1]));
            }
        }
    }

    // epilogue: fp16 stores (g_Ah gets +b3, g_Bh raw)
    #pragma unroll
    for (int mt = 0; mt < 2; mt++) {
        const int r0 = m0 + mt*16 + (lane >> 2);
        const int iAr = i0 + r0, iBr = i0 + r0 + 8;
        #pragma unroll
        for (int nt = 0; nt < 8; nt++) {
            const int c = n0 + nt * 8 + (lane & 3) * 2;
            if (c < 128) {
                const float2 bb = *(const float2*)(b3 + c);
                __half2 h0 = __floats2half2_rn(d[mt][nt][0] + bb.x,
                                               d[mt][nt][1] + bb.y);
                __half2 h1 = __floats2half2_rn(d[mt][nt][2] + bb.x,
                                               d[mt][nt][3] + bb.y);
                *(uint32_t*)(g_Ah + (size_t)iAr * 128 + c) = *(uint32_t*)&h0;
                *(uint32_t*)(g_Ah + (size_t)iBr * 128 + c) = *(uint32_t*)&h1;
            } else {
                __half2 h0 = __floats2half2_rn(d[mt][nt][0], d[mt][nt][1]);
                __half2 h1 = __floats2half2_rn(d[mt][nt][2], d[mt][nt][3]);
                *(uint32_t*)(g_Bh + (size_t)iAr * 128 + (c - 128)) = *(uint32_t*)&h0;
                *(uint32_t*)(g_Bh + (size_t)iBr * 128 + (c - 128)) = *(uint32_t*)&h1;
            }
        }
    }
}

// ---------------- Kernel 4: EdgeConv2 fp16 mma, M=128/CTA, 512 thr ----------
#define A_ELEMS (128 * PADK)
#define B_ELEMS (256 * PADK)
#define CONV2_SMEM ((A_ELEMS + B_ELEMS) * 2)

__global__ __launch_bounds__(512, 1) void conv2m_kernel(
    const float* __restrict__ b4, float* __restrict__ out)
{
    extern __shared__ __align__(16) char smem[];
    __half* sA = (__half*)smem;
    __half* sB = sA + A_ELEMS;

    const int t    = threadIdx.x;
    const int lane = t & 31;
    const int w    = t >> 5;           // 16 warps
    const int p0   = blockIdx.x * 16;

    // ---- build B tile: full W4^T fp16 [256][128], 512 threads ----
    {
        const int row = t >> 1, part = (t & 1) * 8;
        const uint4* s4 = (const uint4*)(g_w4h + (size_t)row * 128);
        uint4* d4 = (uint4*)(sB + row * PADK);
        #pragma unroll
        for (int g = 0; g < 8; g++) d4[part + g] = s4[part + g];
    }
    // ---- build A tile: gather fp16 + half2 add/relu ----
    {
        const int r = t >> 2, q = t & 3;       // 128 rows x 4 thr
        const int i = p0 + (r >> 3);
        const int j = g_knn[i * KNN + (r & 7)];
        const uint4* pa = (const uint4*)(g_Ah + (size_t)i * 128);
        const uint4* pb = (const uint4*)(g_Bh + (size_t)j * 128);
        uint4* dst = (uint4*)(sA + r * PADK);
        const __half2 z2 = __half2half2(__ushort_as_half(0));
        #pragma unroll
        for (int g = 0; g < 4; g++) {
            uint4 av = pa[q*4 + g];
            uint4 bv = pb[q*4 + g];
            uint4 o;
            __half2 s;
            s = __hmax2(__hadd2(*(__half2*)&av.x, *(__half2*)&bv.x), z2); o.x = *(uint32_t*)&s;
            s = __hmax2(__hadd2(*(__half2*)&av.y, *(__half2*)&bv.y), z2); o.y = *(uint32_t*)&s;
            s = __hmax2(__hadd2(*(__half2*)&av.z, *(__half2*)&bv.z), z2); o.z = *(uint32_t*)&s;
            s = __hmax2(__hadd2(*(__half2*)&av.w, *(__half2*)&bv.w), z2); o.w = *(uint32_t*)&s;
            dst[q*4 + g] = o;
        }
    }
    __syncthreads();

    // ---- MMA mainloop: 16 warps = 4(M) x 4(N); warp tile 32M x 64N ----
    const int mw  = w & 3;
    const int nwp = w >> 2;
    const int m0  = mw * 32;
    const int n0  = nwp * 64;

    const uint32_t sA32 = smem_u32(sA), sB32 = smem_u32(sB);
    const uint32_t aoff = ((uint32_t)(m0 + (lane & 15)) * PADK +
                           ((lane >> 4) & 1) * 8) * 2;
    const uint32_t boff = ((uint32_t)(n0 + ((lane >> 4) & 1) * 8 + (lane & 7)) * PADK +
                           ((lane >> 3) & 1) * 8) * 2;

    float d[2][8][4];
    #pragma unroll
    for (int mt = 0; mt < 2; mt++)
        #pragma unroll
        for (int nt = 0; nt < 8; nt++)
            { d[mt][nt][0]=0.f; d[mt][nt][1]=0.f; d[mt][nt][2]=0.f; d[mt][nt][3]=0.f; }

    #pragma unroll
    for (int k16 = 0; k16 < 8; k16++) {
        const uint32_t kb = k16 * 32;
        uint32_t a[2][4];
        #pragma unroll
        for (int mt = 0; mt < 2; mt++) {
            asm volatile(
                "ldmatrix.sync.aligned.m8n8.x4.shared.b16 {%0,%1,%2,%3}, [%4];"
                : "=r"(a[mt][0]), "=r"(a[mt][1]), "=r"(a[mt][2]), "=r"(a[mt][3])
                : "r"(sA32 + aoff + (uint32_t)mt * (16 * PADK * 2) + kb));
        }
        uint32_t b[16];
        #pragma unroll
        for (int ntp = 0; ntp < 4; ntp++) {
            asm volatile(
                "ldmatrix.sync.aligned.m8n8.x4.shared.b16 {%0,%1,%2,%3}, [%4];"
                : "=r"(b[ntp*4]), "=r"(b[ntp*4+1]), "=r"(b[ntp*4+2]), "=r"(b[ntp*4+3])
                : "r"(sB32 + boff + (uint32_t)ntp * (16 * PADK * 2) + kb));
        }
        #pragma unroll
        for (int mt = 0; mt < 2; mt++) {
            #pragma unroll
            for (int nt = 0; nt < 8; nt++) {
                const int bi = (nt >> 1) * 4 + (nt & 1) * 2;
                asm volatile(
                    "mma.sync.aligned.m16n8k16.row.col.f32.f16.f16.f32 "
                    "{%0,%1,%2,%3}, {%4,%5,%6,%7}, {%8,%9}, {%0,%1,%2,%3};"
                    : "+f"(d[mt][nt][0]), "+f"(d[mt][nt][1]),
                      "+f"(d[mt][nt][2]), "+f"(d[mt][nt][3])
                    : "r"(a[mt][0]), "r"(a[mt][1]), "r"(a[mt][2]), "r"(a[mt][3]),
                      "r"(b[bi]), "r"(b[bi+1]));
            }
        }
    }

    // ---- epilogue: max over 8 edge rows (lane bits [4:2]) ----
    #pragma unroll
    for (int mt = 0; mt < 2; mt++) {
        #pragma unroll
        for (int nt = 0; nt < 8; nt++) {
            float v0 = d[mt][nt][0], v1 = d[mt][nt][1];
            float v2 = d[mt][nt][2], v3 = d[mt][nt][3];
            #pragma unroll
            for (int off = 4; off <= 16; off <<= 1) {
                v0 = fmaxf(v0, __shfl_xor_sync(0xFFFFFFFFu, v0, off));
                v1 = fmaxf(v1, __shfl_xor_sync(0xFFFFFFFFu, v1, off));
                v2 = fmaxf(v2, __shfl_xor_sync(0xFFFFFFFFu, v2, off));
                v3 = fmaxf(v3, __shfl_xor_sync(0xFFFFFFFFu, v3, off));
            }
            if (lane < 4) {
                const int c = n0 + nt * 8 + lane * 2;
                const float2 bb = *(const float2*)(b4 + c);
                const int pbase = p0 + mw * 4 + mt * 2;
                float2 o0; o0.x = v0 + bb.x; o0.y = v1 + bb.y;
                float2 o1; o1.x = v2 + bb.x; o1.y = v3 + bb.y;
                *(float2*)(out + (size_t)(pbase    ) * 256 + c) = o0;
                *(float2*)(out + (size_t)(pbase + 1) * 256 + c) = o1;
            }
        }
    }
}

// ---------------- launch -----------------------------------------------------
extern "C" void kernel_launch(void* const* d_in, const int* in_sizes, int n_in,
                              void* d_out, int out_size) {
    const float* pts = (const float*)d_in[0];
    const float* W1  = (const float*)d_in[1];
    const float* b1  = (const float*)d_in[2];
    const float* W2  = (const float*)d_in[3];
    const float* b2  = (const float*)d_in[4];
    const float* W3  = (const float*)d_in[5];
    const float* b3  = (const float*)d_in[6];
    const float* W4  = (const float*)d_in[7];
    const float* b4  = (const float*)d_in[8];
    float* out = (float*)d_out;

    cudaFuncSetAttribute(pre2t_kernel,
                         cudaFuncAttributeMaxDynamicSharedMemorySize, PRE2_SMEM);
    cudaFuncSetAttribute(conv2m_kernel,
                         cudaFuncAttributeMaxDynamicSharedMemorySize, CONV2_SMEM);

    knn_kernel   <<<NPTS/8, 256>>>(pts, W2, W3, W4);
    conv1_kernel <<<NPTS/16, 256>>>(pts, W1, b1, b2);
    pre2t_kernel <<<NPTS/64, 256, PRE2_SMEM>>>(b3);
    conv2m_kernel<<<NPTS/16, 512, CONV2_SMEM>>>(b4, out);
}

// round 13
// speedup vs baseline: 1.5844x; 1.0805x over previous
#include <cuda_runtime.h>
#include <cuda_fp16.h>
#include <cstdint>

#define NPTS 8192
#define KNN  8

// ---------------- scratch (device globals: no allocations allowed) ----------
__device__ int   g_knn[NPTS * KNN];
__device__ unsigned short g_x1h[NPTS * 128];  // edgeconv1 output fp16 [i][k]
__device__ unsigned short g_Ah[NPTS * 128];   // fp16: x1 @ (W3a-W3b) + b3
__device__ unsigned short g_Bh[NPTS * 128];   // fp16: x1 @ W3b
__device__ unsigned short g_w2h[128 * 64];    // W2^T fp16 [c][u]
__device__ unsigned short g_w3h[256 * 128];   // [Wd^T ; Wb^T] fp16 [n][k]
__device__ unsigned short g_w4h[256 * 128];   // W4^T fp16 [c][k]

// ---------------- helpers ----------------------------------------------------
__device__ __forceinline__ uint32_t smem_u32(const void* p) {
    uint32_t a;
    asm("{ .reg .u64 t; cvta.to.shared.u64 t, %1; cvt.u32.u64 %0, t; }"
        : "=r"(a) : "l"(p));
    return a;
}

// ---------------- Kernels 0a-0c: weight fp16 conversions (launch slots 1-3) -
__global__ __launch_bounds__(256) void w2conv_kernel(const float* __restrict__ W2) {
    int idx = blockIdx.x * 256 + threadIdx.x;      // 8192
    int c = idx >> 6, u = idx & 63;
    g_w2h[idx] = __half_as_ushort(__float2half_rn(W2[u*128 + c]));
}
__global__ __launch_bounds__(256) void w3conv_kernel(const float* __restrict__ W3) {
    int idx = blockIdx.x * 256 + threadIdx.x;      // 16384
    int k = idx >> 7, c = idx & 127;
    float wa = W3[k*128 + c];
    float wb = W3[(k+128)*128 + c];
    g_w3h[c*128 + k]       = __half_as_ushort(__float2half_rn(wa - wb));
    g_w3h[(128+c)*128 + k] = __half_as_ushort(__float2half_rn(wb));
}
__global__ __launch_bounds__(256) void w4conv_kernel(const float* __restrict__ W4) {
    int idx = blockIdx.x * 256 + threadIdx.x;      // 32768
    int k = idx >> 8, c = idx & 255;
    g_w4h[c*128 + k] = __half_as_ushort(__float2half_rn(W4[k*256 + c]));
}

// ---------------- Kernel 1: KNN (scalar, warp-shared threshold gate) --------
__global__ __launch_bounds__(256) void knn_kernel(const float* __restrict__ pts) {
    const int TS = 2048;
    __shared__ float4 sp[TS];
    const int lane = threadIdx.x & 31;
    const int warp = threadIdx.x >> 5;
    const int qi = blockIdx.x * 8 + warp;

    const float qx = pts[qi*3+0], qy = pts[qi*3+1], qz = pts[qi*3+2];
    const float ax = -2.0f*qx, ay = -2.0f*qy, az = -2.0f*qz;

    const float INF = 3.4028235e38f;
    float    ld[8]; unsigned int li[8];
    #pragma unroll
    for (int q = 0; q < 8; q++) { ld[q] = INF; li[q] = 0xFFFFFFFFu; }

    for (int base = 0; base < NPTS; base += TS) {
        __syncthreads();
        for (int t = threadIdx.x; t < TS; t += 256) {
            float x = pts[(base+t)*3+0];
            float y = pts[(base+t)*3+1];
            float z = pts[(base+t)*3+2];
            sp[t] = make_float4(x, y, z, x*x + y*y + z*z);
        }
        __syncthreads();

        for (int jb = 0; jb < TS; jb += 256) {
            // warp-shared gate: T = min over lanes of ld[7]  (valid: any
            // lane's 8th-best >= warp's true 8th-best)
            float T = ld[7];
            #pragma unroll
            for (int off = 16; off; off >>= 1)
                T = fminf(T, __shfl_xor_sync(0xFFFFFFFFu, T, off));

            float dd[8];
            #pragma unroll
            for (int q = 0; q < 8; q++) {
                float4 p = sp[jb + q*32 + lane];
                dd[q] = fmaf(ax, p.x, fmaf(ay, p.y, fmaf(az, p.z, p.w)));
            }
            float m01 = fminf(dd[0], dd[1]), m23 = fminf(dd[2], dd[3]);
            float m45 = fminf(dd[4], dd[5]), m67 = fminf(dd[6], dd[7]);
            float mn = fminf(fminf(m01, m23), fminf(m45, m67));
            if (mn < T) {
                #pragma unroll
                for (int q = 0; q < 8; q++) {
                    float x = dd[q];
                    if (x < T) {           // T <= ld[7], so bubble is valid
                        unsigned int ix = (unsigned int)(base + jb + q*32 + lane);
                        ld[7] = x; li[7] = ix;
                        #pragma unroll
                        for (int s = 6; s >= 0; s--) {
                            bool sw = ld[s+1] < ld[s];
                            float  td = sw ? ld[s] : ld[s+1];
                            unsigned int ti = sw ? li[s] : li[s+1];
                            ld[s]   = sw ? ld[s+1] : ld[s];
                            li[s]   = sw ? li[s+1] : li[s];
                            ld[s+1] = td; li[s+1] = ti;
                        }
                    }
                }
            }
        }
    }

    unsigned long long k[8];
    #pragma unroll
    for (int q = 0; q < 8; q++) {
        unsigned int ob = __float_as_uint(ld[q]);
        ob ^= ((unsigned int)((int)ob >> 31)) | 0x80000000u;
        k[q] = ((unsigned long long)ob << 32) | li[q];
    }
    #pragma unroll
    for (int r = 0; r < KNN; r++) {
        unsigned long long m = k[0];
        #pragma unroll
        for (int off = 16; off; off >>= 1) {
            unsigned long long o = __shfl_xor_sync(0xFFFFFFFFu, m, off);
            if (o < m) m = o;
        }
        if (k[0] == m) {
            #pragma unroll
            for (int s = 0; s < 7; s++) k[s] = k[s+1];
            k[7] = 0xFFFFFFFFFFFFFFFFULL;
        }
        if (lane == 0) g_knn[qi*KNN + r] = (int)(m & 0xFFFFFFFFu);
    }
}

// ---------------- Kernel 2: EdgeConv1, layer2 on tensor cores ---------------
#define PADK2 72
__global__ __launch_bounds__(256) void conv1_kernel(
    const float* __restrict__ pts,
    const float* __restrict__ W1, const float* __restrict__ b1,
    const float* __restrict__ b2)
{
    __shared__ float  se[16][8][6];
    __shared__ __half sE[128 * PADK2];
    __shared__ __half sW[128 * PADK2];
    const int t    = threadIdx.x;
    const int lane = t & 31;
    const int w    = t >> 5;
    const int p0   = blockIdx.x * 16;

    {
        #pragma unroll
        for (int g = 0; g < 4; g++) {
            int idx = t + g*256;
            int row = idx >> 3, part = idx & 7;
            uint4 v = *((const uint4*)(g_w2h + row*64) + part);
            *((uint4*)(sW + row*PADK2) + part) = v;
        }
    }
    if (t < 128) {
        int p = t >> 3, e = t & 7;
        int i = p0 + p;
        int j = g_knn[i*KNN + e];
        float xi0 = pts[i*3+0], xi1 = pts[i*3+1], xi2 = pts[i*3+2];
        float xj0 = pts[j*3+0], xj1 = pts[j*3+1], xj2 = pts[j*3+2];
        se[p][e][0] = xi0; se[p][e][1] = xi1; se[p][e][2] = xi2;
        se[p][e][3] = xj0 - xi0; se[p][e][4] = xj1 - xi1; se[p][e][5] = xj2 - xi2;
    }

    // hoist W1/b1: u fixed per thread
    const int u = t & 63;
    float w1r[6];
    #pragma unroll
    for (int f = 0; f < 6; f++) w1r[f] = W1[f*64 + u];
    const float b1r = b1[u];
    __syncthreads();

    #pragma unroll
    for (int r = 0; r < 32; r++) {
        int pe = (t >> 6) + r * 4;         // 0..127
        int p = pe >> 3, e = pe & 7;
        float acc = b1r;
        #pragma unroll
        for (int f = 0; f < 6; f++) acc += se[p][e][f] * w1r[f];
        sE[pe * PADK2 + u] = __float2half_rn(fmaxf(acc, 0.0f));
    }
    __syncthreads();

    const int mw = w & 1, nw = w >> 1;
    const int m0 = mw * 64;
    const int n0 = nw * 32;

    const uint32_t sE32 = smem_u32(sE), sW32 = smem_u32(sW);
    const uint32_t aoff = ((uint32_t)(m0 + (lane & 15)) * PADK2 +
                           ((lane >> 4) & 1) * 8) * 2;
    const uint32_t boff = ((uint32_t)(n0 + ((lane >> 4) & 1) * 8 + (lane & 7)) * PADK2 +
                           ((lane >> 3) & 1) * 8) * 2;

    float d[4][4][4];
    #pragma unroll
    for (int mt = 0; mt < 4; mt++)
        #pragma unroll
        for (int nt = 0; nt < 4; nt++)
            { d[mt][nt][0]=0.f; d[mt][nt][1]=0.f; d[mt][nt][2]=0.f; d[mt][nt][3]=0.f; }

    #pragma unroll
    for (int k16 = 0; k16 < 4; k16++) {
        const uint32_t kb = k16 * 32;
        uint32_t a[4][4];
        #pragma unroll
        for (int mt = 0; mt < 4; mt++) {
            asm volatile(
                "ldmatrix.sync.aligned.m8n8.x4.shared.b16 {%0,%1,%2,%3}, [%4];"
                : "=r"(a[mt][0]), "=r"(a[mt][1]), "=r"(a[mt][2]), "=r"(a[mt][3])
                : "r"(sE32 + aoff + (uint32_t)mt * (16 * PADK2 * 2) + kb));
        }
        uint32_t b[8];
        #pragma unroll
        for (int ntp = 0; ntp < 2; ntp++) {
            asm volatile(
                "ldmatrix.sync.aligned.m8n8.x4.shared.b16 {%0,%1,%2,%3}, [%4];"
                : "=r"(b[ntp*4]), "=r"(b[ntp*4+1]), "=r"(b[ntp*4+2]), "=r"(b[ntp*4+3])
                : "r"(sW32 + boff + (uint32_t)ntp * (16 * PADK2 * 2) + kb));
        }
        #pragma unroll
        for (int mt = 0; mt < 4; mt++) {
            #pragma unroll
            for (int nt = 0; nt < 4; nt++) {
                const int bi = (nt >> 1) * 4 + (nt & 1) * 2;
                asm volatile(
                    "mma.sync.aligned.m16n8k16.row.col.f32.f16.f16.f32 "
                    "{%0,%1,%2,%3}, {%4,%5,%6,%7}, {%8,%9}, {%0,%1,%2,%3};"
                    : "+f"(d[mt][nt][0]), "+f"(d[mt][nt][1]),
                      "+f"(d[mt][nt][2]), "+f"(d[mt][nt][3])
                    : "r"(a[mt][0]), "r"(a[mt][1]), "r"(a[mt][2]), "r"(a[mt][3]),
                      "r"(b[bi]), "r"(b[bi+1]));
            }
        }
    }

    #pragma unroll
    for (int mt = 0; mt < 4; mt++) {
        #pragma unroll
        for (int nt = 0; nt < 4; nt++) {
            float v0 = d[mt][nt][0], v1 = d[mt][nt][1];
            float v2 = d[mt][nt][2], v3 = d[mt][nt][3];
            #pragma unroll
            for (int off = 4; off <= 16; off <<= 1) {
                v0 = fmaxf(v0, __shfl_xor_sync(0xFFFFFFFFu, v0, off));
                v1 = fmaxf(v1, __shfl_xor_sync(0xFFFFFFFFu, v1, off));
                v2 = fmaxf(v2, __shfl_xor_sync(0xFFFFFFFFu, v2, off));
                v3 = fmaxf(v3, __shfl_xor_sync(0xFFFFFFFFu, v3, off));
            }
            if (lane < 4) {
                const int c = n0 + nt * 8 + lane * 2;
                const float2 bb = *(const float2*)(b2 + c);
                const int pA = p0 + mw * 8 + mt * 2;
                __half2 hA = __floats2half2_rn(fmaxf(v0 + bb.x, 0.0f),
                                               fmaxf(v1 + bb.y, 0.0f));
                __half2 hB = __floats2half2_rn(fmaxf(v2 + bb.x, 0.0f),
                                               fmaxf(v3 + bb.y, 0.0f));
                *(uint32_t*)(g_x1h + (size_t)(pA    ) * 128 + c) = *(uint32_t*)&hA;
                *(uint32_t*)(g_x1h + (size_t)(pA + 1) * 128 + c) = *(uint32_t*)&hB;
            }
        }
    }
}

// ---------------- Kernel 3: pre2 as fp16 GEMM, fp16 outputs -----------------
#define PADK 136
#define P_A_ELEMS (64  * PADK)
#define P_B_ELEMS (256 * PADK)
#define PRE2_SMEM ((P_A_ELEMS + P_B_ELEMS) * 2)

__global__ __launch_bounds__(256, 2) void pre2t_kernel(const float* __restrict__ b3)
{
    extern __shared__ __align__(16) char smem[];
    __half* sA = (__half*)smem;
    __half* sB = sA + P_A_ELEMS;

    const int t    = threadIdx.x;
    const int lane = t & 31;
    const int w    = t >> 5;
    const int i0   = blockIdx.x * 64;

    {
        const int r = t >> 2, q = t & 3;
        #pragma unroll
        for (int g = 0; g < 4; g++) {
            uint4 v = *((const uint4*)(g_x1h + (size_t)(i0 + r) * 128) + q*4 + g);
            *((uint4*)(sA + r * PADK) + q*4 + g) = v;
        }
    }
    {
        const uint4* s4 = (const uint4*)(g_w3h + (size_t)t * 128);
        uint4* d4 = (uint4*)(sB + t * PADK);
        #pragma unroll
        for (int kg = 0; kg < 16; kg++) d4[kg] = s4[kg];
    }
    __syncthreads();

    const int mw  = w & 1;
    const int nwp = w >> 1;
    const int m0  = mw * 32;
    const int n0  = nwp * 64;

    const uint32_t sA32 = smem_u32(sA), sB32 = smem_u32(sB);
    const uint32_t aoff = ((uint32_t)(m0 + (lane & 15)) * PADK +
                           ((lane >> 4) & 1) * 8) * 2;
    const uint32_t boff = ((uint32_t)(n0 + ((lane >> 4) & 1) * 8 + (lane & 7)) * PADK +
                           ((lane >> 3) & 1) * 8) * 2;

    float d[2][8][4];
    #pragma unroll
    for (int mt = 0; mt < 2; mt++)
        #pragma unroll
        for (int nt = 0; nt < 8; nt++)
            { d[mt][nt][0]=0.f; d[mt][nt][1]=0.f; d[mt][nt][2]=0.f; d[mt][nt][3]=0.f; }

    #pragma unroll
    for (int k16 = 0; k16 < 8; k16++) {
        const uint32_t kb = k16 * 32;
        uint32_t a[2][4];
        #pragma unroll
        for (int mt = 0; mt < 2; mt++) {
            asm volatile(
                "ldmatrix.sync.aligned.m8n8.x4.shared.b16 {%0,%1,%2,%3}, [%4];"
                : "=r"(a[mt][0]), "=r"(a[mt][1]), "=r"(a[mt][2]), "=r"(a[mt][3])
                : "r"(sA32 + aoff + (uint32_t)mt * (16 * PADK * 2) + kb));
        }
        uint32_t b[16];
        #pragma unroll
        for (int ntp = 0; ntp < 4; ntp++) {
            asm volatile(
                "ldmatrix.sync.aligned.m8n8.x4.shared.b16 {%0,%1,%2,%3}, [%4];"
                : "=r"(b[ntp*4]), "=r"(b[ntp*4+1]), "=r"(b[ntp*4+2]), "=r"(b[ntp*4+3])
                : "r"(sB32 + boff + (uint32_t)ntp * (16 * PADK * 2) + kb));
        }
        #pragma unroll
        for (int mt = 0; mt < 2; mt++) {
            #pragma unroll
            for (int nt = 0; nt < 8; nt++) {
                const int bi = (nt >> 1) * 4 + (nt & 1) * 2;
                asm volatile(
                    "mma.sync.aligned.m16n8k16.row.col.f32.f16.f16.f32 "
                    "{%0,%1,%2,%3}, {%4,%5,%6,%7}, {%8,%9}, {%0,%1,%2,%3};"
                    : "+f"(d[mt][nt][0]), "+f"(d[mt][nt][1]),
                      "+f"(d[mt][nt][2]), "+f"(d[mt][nt][3])
                    : "r"(a[mt][0]), "r"(a[mt][1]), "r"(a[mt][2]), "r"(a[mt][3]),
                      "r"(b[bi]), "r"(b[bi+1]));
            }
        }
    }

    #pragma unroll
    for (int mt = 0; mt < 2; mt++) {
        const int r0 = m0 + mt*16 + (lane >> 2);
        const int iAr = i0 + r0, iBr = i0 + r0 + 8;
        #pragma unroll
        for (int nt = 0; nt < 8; nt++) {
            const int c = n0 + nt * 8 + (lane & 3) * 2;
            if (c < 128) {
                const float2 bb = *(const float2*)(b3 + c);
                __half2 h0 = __floats2half2_rn(d[mt][nt][0] + bb.x,
                                               d[mt][nt][1] + bb.y);
                __half2 h1 = __floats2half2_rn(d[mt][nt][2] + bb.x,
                                               d[mt][nt][3] + bb.y);
                *(uint32_t*)(g_Ah + (size_t)iAr * 128 + c) = *(uint32_t*)&h0;
                *(uint32_t*)(g_Ah + (size_t)iBr * 128 + c) = *(uint32_t*)&h1;
            } else {
                __half2 h0 = __floats2half2_rn(d[mt][nt][0], d[mt][nt][1]);
                __half2 h1 = __floats2half2_rn(d[mt][nt][2], d[mt][nt][3]);
                *(uint32_t*)(g_Bh + (size_t)iAr * 128 + (c - 128)) = *(uint32_t*)&h0;
                *(uint32_t*)(g_Bh + (size_t)iBr * 128 + (c - 128)) = *(uint32_t*)&h1;
            }
        }
    }
}

// ---------------- Kernel 4: EdgeConv2 fp16 mma, M=128/CTA, 512 thr ----------
#define A_ELEMS (128 * PADK)
#define B_ELEMS (256 * PADK)
#define CONV2_SMEM ((A_ELEMS + B_ELEMS) * 2)

__global__ __launch_bounds__(512, 1) void conv2m_kernel(
    const float* __restrict__ b4, float* __restrict__ out)
{
    extern __shared__ __align__(16) char smem[];
    __half* sA = (__half*)smem;
    __half* sB = sA + A_ELEMS;

    const int t    = threadIdx.x;
    const int lane = t & 31;
    const int w    = t >> 5;
    const int p0   = blockIdx.x * 16;

    {
        const int row = t >> 1, part = (t & 1) * 8;
        const uint4* s4 = (const uint4*)(g_w4h + (size_t)row * 128);
        uint4* d4 = (uint4*)(sB + row * PADK);
        #pragma unroll
        for (int g = 0; g < 8; g++) d4[part + g] = s4[part + g];
    }
    {
        const int r = t >> 2, q = t & 3;
        const int i = p0 + (r >> 3);
        const int j = g_knn[i * KNN + (r & 7)];
        const uint4* pa = (const uint4*)(g_Ah + (size_t)i * 128);
        const uint4* pb = (const uint4*)(g_Bh + (size_t)j * 128);
        uint4* dst = (uint4*)(sA + r * PADK);
        const __half2 z2 = __half2half2(__ushort_as_half(0));
        #pragma unroll
        for (int g = 0; g < 4; g++) {
            uint4 av = pa[q*4 + g];
            uint4 bv = pb[q*4 + g];
            uint4 o;
            __half2 s;
            s = __hmax2(__hadd2(*(__half2*)&av.x, *(__half2*)&bv.x), z2); o.x = *(uint32_t*)&s;
            s = __hmax2(__hadd2(*(__half2*)&av.y, *(__half2*)&bv.y), z2); o.y = *(uint32_t*)&s;
            s = __hmax2(__hadd2(*(__half2*)&av.z, *(__half2*)&bv.z), z2); o.z = *(uint32_t*)&s;
            s = __hmax2(__hadd2(*(__half2*)&av.w, *(__half2*)&bv.w), z2); o.w = *(uint32_t*)&s;
            dst[q*4 + g] = o;
        }
    }
    __syncthreads();

    const int mw  = w & 3;
    const int nwp = w >> 2;
    const int m0  = mw * 32;
    const int n0  = nwp * 64;

    const uint32_t sA32 = smem_u32(sA), sB32 = smem_u32(sB);
    const uint32_t aoff = ((uint32_t)(m0 + (lane & 15)) * PADK +
                           ((lane >> 4) & 1) * 8) * 2;
    const uint32_t boff = ((uint32_t)(n0 + ((lane >> 4) & 1) * 8 + (lane & 7)) * PADK +
                           ((lane >> 3) & 1) * 8) * 2;

    float d[2][8][4];
    #pragma unroll
    for (int mt = 0; mt < 2; mt++)
        #pragma unroll
        for (int nt = 0; nt < 8; nt++)
            { d[mt][nt][0]=0.f; d[mt][nt][1]=0.f; d[mt][nt][2]=0.f; d[mt][nt][3]=0.f; }

    #pragma unroll
    for (int k16 = 0; k16 < 8; k16++) {
        const uint32_t kb = k16 * 32;
        uint32_t a[2][4];
        #pragma unroll
        for (int mt = 0; mt < 2; mt++) {
            asm volatile(
                "ldmatrix.sync.aligned.m8n8.x4.shared.b16 {%0,%1,%2,%3}, [%4];"
                : "=r"(a[mt][0]), "=r"(a[mt][1]), "=r"(a[mt][2]), "=r"(a[mt][3])
                : "r"(sA32 + aoff + (uint32_t)mt * (16 * PADK * 2) + kb));
        }
        uint32_t b[16];
        #pragma unroll
        for (int ntp = 0; ntp < 4; ntp++) {
            asm volatile(
                "ldmatrix.sync.aligned.m8n8.x4.shared.b16 {%0,%1,%2,%3}, [%4];"
                : "=r"(b[ntp*4]), "=r"(b[ntp*4+1]), "=r"(b[ntp*4+2]), "=r"(b[ntp*4+3])
                : "r"(sB32 + boff + (uint32_t)ntp * (16 * PADK * 2) + kb));
        }
        #pragma unroll
        for (int mt = 0; mt < 2; mt++) {
            #pragma unroll
            for (int nt = 0; nt < 8; nt++) {
                const int bi = (nt >> 1) * 4 + (nt & 1) * 2;
                asm volatile(
                    "mma.sync.aligned.m16n8k16.row.col.f32.f16.f16.f32 "
                    "{%0,%1,%2,%3}, {%4,%5,%6,%7}, {%8,%9}, {%0,%1,%2,%3};"
                    : "+f"(d[mt][nt][0]), "+f"(d[mt][nt][1]),
                      "+f"(d[mt][nt][2]), "+f"(d[mt][nt][3])
                    : "r"(a[mt][0]), "r"(a[mt][1]), "r"(a[mt][2]), "r"(a[mt][3]),
                      "r"(b[bi]), "r"(b[bi+1]));
            }
        }
    }

    #pragma unroll
    for (int mt = 0; mt < 2; mt++) {
        #pragma unroll
        for (int nt = 0; nt < 8; nt++) {
            float v0 = d[mt][nt][0], v1 = d[mt][nt][1];
            float v2 = d[mt][nt][2], v3 = d[mt][nt][3];
            #pragma unroll
            for (int off = 4; off <= 16; off <<= 1) {
                v0 = fmaxf(v0, __shfl_xor_sync(0xFFFFFFFFu, v0, off));
                v1 = fmaxf(v1, __shfl_xor_sync(0xFFFFFFFFu, v1, off));
                v2 = fmaxf(v2, __shfl_xor_sync(0xFFFFFFFFu, v2, off));
                v3 = fmaxf(v3, __shfl_xor_sync(0xFFFFFFFFu, v3, off));
            }
            if (lane < 4) {
                const int c = n0 + nt * 8 + lane * 2;
                const float2 bb = *(const float2*)(b4 + c);
                const int pbase = p0 + mw * 4 + mt * 2;
                float2 o0; o0.x = v0 + bb.x; o0.y = v1 + bb.y;
                float2 o1; o1.x = v2 + bb.x; o1.y = v3 + bb.y;
                *(float2*)(out + (size_t)(pbase    ) * 256 + c) = o0;
                *(float2*)(out + (size_t)(pbase + 1) * 256 + c) = o1;
            }
        }
    }
}

// ---------------- launch -----------------------------------------------------
extern "C" void kernel_launch(void* const* d_in, const int* in_sizes, int n_in,
                              void* d_out, int out_size) {
    const float* pts = (const float*)d_in[0];
    const float* W1  = (const float*)d_in[1];
    const float* b1  = (const float*)d_in[2];
    const float* W2  = (const float*)d_in[3];
    const float* b2  = (const float*)d_in[4];
    const float* W3  = (const float*)d_in[5];
    const float* b3  = (const float*)d_in[6];
    const float* W4  = (const float*)d_in[7];
    const float* b4  = (const float*)d_in[8];
    float* out = (float*)d_out;

    cudaFuncSetAttribute(pre2t_kernel,
                         cudaFuncAttributeMaxDynamicSharedMemorySize, PRE2_SMEM);
    cudaFuncSetAttribute(conv2m_kernel,
                         cudaFuncAttributeMaxDynamicSharedMemorySize, CONV2_SMEM);

    w2conv_kernel<<<32, 256>>>(W2);
    w3conv_kernel<<<64, 256>>>(W3);
    w4conv_kernel<<<128, 256>>>(W4);
    knn_kernel   <<<NPTS/8, 256>>>(pts);     // 4th launch -> profiled
    conv1_kernel <<<NPTS/16, 256>>>(pts, W1, b1, b2);
    pre2t_kernel <<<NPTS/64, 256, PRE2_SMEM>>>(b3);
    conv2m_kernel<<<NPTS/16, 512, CONV2_SMEM>>>(b4, out);
}

// round 16
// speedup vs baseline: 2.0312x; 1.2820x over previous
#include <cuda_runtime.h>
#include <cuda_fp16.h>
#include <cstdint>

#define NPTS 8192
#define KNN  8

// ---------------- scratch (device globals: no allocations allowed) ----------
__device__ int   g_knn[NPTS * KNN];
__device__ unsigned short g_x1h[NPTS * 128];  // edgeconv1 output fp16 [i][k]
__device__ unsigned short g_Ah[NPTS * 128];   // fp16: x1 @ (W3a-W3b) + b3
__device__ unsigned short g_Bh[NPTS * 128];   // fp16: x1 @ W3b
__device__ unsigned short g_w2h[128 * 64];    // W2^T fp16 [c][u]
__device__ unsigned short g_w3h[256 * 128];   // [Wd^T ; Wb^T] fp16 [n][k]
__device__ unsigned short g_w4h[256 * 128];   // W4^T fp16 [c][k]

// ---------------- helpers ----------------------------------------------------
__device__ __forceinline__ uint32_t smem_u32(const void* p) {
    uint32_t a;
    asm("{ .reg .u64 t; cvta.to.shared.u64 t, %1; cvt.u32.u64 %0, t; }"
        : "=r"(a) : "l"(p));
    return a;
}

// ---------------- Kernels 0a-0c: weight fp16 conversions (launch slots 1-3) -
__global__ __launch_bounds__(256) void w2conv_kernel(const float* __restrict__ W2) {
    int idx = blockIdx.x * 256 + threadIdx.x;      // 8192
    int c = idx >> 6, u = idx & 63;
    g_w2h[idx] = __half_as_ushort(__float2half_rn(W2[u*128 + c]));
}
__global__ __launch_bounds__(256) void w3conv_kernel(const float* __restrict__ W3) {
    int idx = blockIdx.x * 256 + threadIdx.x;      // 16384
    int k = idx >> 7, c = idx & 127;
    float wa = W3[k*128 + c];
    float wb = W3[(k+128)*128 + c];
    g_w3h[c*128 + k]       = __half_as_ushort(__float2half_rn(wa - wb));
    g_w3h[(128+c)*128 + k] = __half_as_ushort(__float2half_rn(wb));
}
__global__ __launch_bounds__(256) void w4conv_kernel(const float* __restrict__ W4) {
    int idx = blockIdx.x * 256 + threadIdx.x;      // 32768
    int k = idx >> 8, c = idx & 255;
    g_w4h[c*128 + k] = __half_as_ushort(__float2half_rn(W4[k*256 + c]));
}

// ---------------- Kernel 1: KNN, warp-distributed sorted top-8 --------------
// Lanes 0..7 hold the warp's running top-8 as sorted u64 (ordered-d, idx)
// keys; threshold refreshed after every insert. Each candidate inserts at
// most once (processed bits retired from the ballot).
__global__ __launch_bounds__(256) void knn_kernel(const float* __restrict__ pts) {
    const int TS = 2048;
    __shared__ float4 sp[TS];
    const int lane = threadIdx.x & 31;
    const int warp = threadIdx.x >> 5;
    const int qi = blockIdx.x * 8 + warp;
    const unsigned FULL = 0xFFFFFFFFu;

    const float qx = pts[qi*3+0], qy = pts[qi*3+1], qz = pts[qi*3+2];
    const float ax = -2.0f*qx, ay = -2.0f*qy, az = -2.0f*qz;

    const float INF = 3.4028235e38f;
    unsigned long long mykey = 0xFFFFFFFFFFFFFFFFULL;  // lanes 0..7 meaningful
    float myd = INF;
    float Tf  = INF;                                   // = myd at lane 7

    for (int base = 0; base < NPTS; base += TS) {
        __syncthreads();
        for (int t = threadIdx.x; t < TS; t += 256) {
            float x = pts[(base+t)*3+0];
            float y = pts[(base+t)*3+1];
            float z = pts[(base+t)*3+2];
            sp[t] = make_float4(x, y, z, x*x + y*y + z*z);
        }
        __syncthreads();

        for (int jb = 0; jb < TS; jb += 256) {
            float dd[8];
            #pragma unroll
            for (int q = 0; q < 8; q++) {
                float4 p = sp[jb + q*32 + lane];
                dd[q] = fmaf(ax, p.x, fmaf(ay, p.y, fmaf(az, p.z, p.w)));
            }
            float m01 = fminf(dd[0], dd[1]), m23 = fminf(dd[2], dd[3]);
            float m45 = fminf(dd[4], dd[5]), m67 = fminf(dd[6], dd[7]);
            float mn = fminf(fminf(m01, m23), fminf(m45, m67));

            if (__any_sync(FULL, mn < Tf)) {
                #pragma unroll
                for (int q = 0; q < 8; q++) {
                    unsigned bal = __ballot_sync(FULL, dd[q] < Tf);
                    while (bal) {
                        const int src = __ffs(bal) - 1;
                        const float kd = __shfl_sync(FULL, dd[q], src);
                        const unsigned kidx =
                            (unsigned)(base + jb + q*32 + src);
                        unsigned ob = __float_as_uint(kd);
                        ob ^= ((unsigned)((int)ob >> 31)) | 0x80000000u;
                        const unsigned long long k =
                            ((unsigned long long)ob << 32) | kidx;
                        // warp insertion-shift into sorted lanes 0..7
                        unsigned long long p = __shfl_up_sync(FULL, mykey, 1);
                        float pd = __shfl_up_sync(FULL, myd, 1);
                        if (lane == 0) { p = 0ULL; pd = -INF; }
                        const bool keep = mykey < k;
                        const bool useP = p > k;
                        mykey = keep ? mykey : (useP ? p  : k);
                        myd   = keep ? myd   : (useP ? pd : kd);
                        Tf = __shfl_sync(FULL, myd, 7);
                        bal &= bal - 1;                          // retire src
                        bal &= __ballot_sync(FULL, dd[q] < Tf);  // re-gate
                    }
                }
            }
        }
    }

    if (lane < 8) g_knn[qi*KNN + lane] = (int)(mykey & 0xFFFFFFFFu);
}

// ---------------- Kernel 2: EdgeConv1, layer2 on tensor cores ---------------
#define PADK2 72
__global__ __launch_bounds__(256) void conv1_kernel(
    const float* __restrict__ pts,
    const float* __restrict__ W1, const float* __restrict__ b1,
    const float* __restrict__ b2)
{
    __shared__ float  se[16][8][6];
    __shared__ __half sE[128 * PADK2];
    __shared__ __half sW[128 * PADK2];
    const int t    = threadIdx.x;
    const int lane = t & 31;
    const int w    = t >> 5;
    const int p0   = blockIdx.x * 16;

    {
        #pragma unroll
        for (int g = 0; g < 4; g++) {
            int idx = t + g*256;
            int row = idx >> 3, part = idx & 7;
            uint4 v = *((const uint4*)(g_w2h + row*64) + part);
            *((uint4*)(sW + row*PADK2) + part) = v;
        }
    }
    if (t < 128) {
        int p = t >> 3, e = t & 7;
        int i = p0 + p;
        int j = g_knn[i*KNN + e];
        float xi0 = pts[i*3+0], xi1 = pts[i*3+1], xi2 = pts[i*3+2];
        float xj0 = pts[j*3+0], xj1 = pts[j*3+1], xj2 = pts[j*3+2];
        se[p][e][0] = xi0; se[p][e][1] = xi1; se[p][e][2] = xi2;
        se[p][e][3] = xj0 - xi0; se[p][e][4] = xj1 - xi1; se[p][e][5] = xj2 - xi2;
    }

    const int u = t & 63;
    float w1r[6];
    #pragma unroll
    for (int f = 0; f < 6; f++) w1r[f] = W1[f*64 + u];
    const float b1r = b1[u];
    __syncthreads();

    #pragma unroll
    for (int r = 0; r < 32; r++) {
        int pe = (t >> 6) + r * 4;
        int p = pe >> 3, e = pe & 7;
        float acc = b1r;
        #pragma unroll
        for (int f = 0; f < 6; f++) acc += se[p][e][f] * w1r[f];
        sE[pe * PADK2 + u] = __float2half_rn(fmaxf(acc, 0.0f));
    }
    __syncthreads();

    const int mw = w & 1, nw = w >> 1;
    const int m0 = mw * 64;
    const int n0 = nw * 32;

    const uint32_t sE32 = smem_u32(sE), sW32 = smem_u32(sW);
    const uint32_t aoff = ((uint32_t)(m0 + (lane & 15)) * PADK2 +
                           ((lane >> 4) & 1) * 8) * 2;
    const uint32_t boff = ((uint32_t)(n0 + ((lane >> 4) & 1) * 8 + (lane & 7)) * PADK2 +
                           ((lane >> 3) & 1) * 8) * 2;

    float d[4][4][4];
    #pragma unroll
    for (int mt = 0; mt < 4; mt++)
        #pragma unroll
        for (int nt = 0; nt < 4; nt++)
            { d[mt][nt][0]=0.f; d[mt][nt][1]=0.f; d[mt][nt][2]=0.f; d[mt][nt][3]=0.f; }

    #pragma unroll
    for (int k16 = 0; k16 < 4; k16++) {
        const uint32_t kb = k16 * 32;
        uint32_t a[4][4];
        #pragma unroll
        for (int mt = 0; mt < 4; mt++) {
            asm volatile(
                "ldmatrix.sync.aligned.m8n8.x4.shared.b16 {%0,%1,%2,%3}, [%4];"
                : "=r"(a[mt][0]), "=r"(a[mt][1]), "=r"(a[mt][2]), "=r"(a[mt][3])
                : "r"(sE32 + aoff + (uint32_t)mt * (16 * PADK2 * 2) + kb));
        }
        uint32_t b[8];
        #pragma unroll
        for (int ntp = 0; ntp < 2; ntp++) {
            asm volatile(
                "ldmatrix.sync.aligned.m8n8.x4.shared.b16 {%0,%1,%2,%3}, [%4];"
                : "=r"(b[ntp*4]), "=r"(b[ntp*4+1]), "=r"(b[ntp*4+2]), "=r"(b[ntp*4+3])
                : "r"(sW32 + boff + (uint32_t)ntp * (16 * PADK2 * 2) + kb));
        }
        #pragma unroll
        for (int mt = 0; mt < 4; mt++) {
            #pragma unroll
            for (int nt = 0; nt < 4; nt++) {
                const int bi = (nt >> 1) * 4 + (nt & 1) * 2;
                asm volatile(
                    "mma.sync.aligned.m16n8k16.row.col.f32.f16.f16.f32 "
                    "{%0,%1,%2,%3}, {%4,%5,%6,%7}, {%8,%9}, {%0,%1,%2,%3};"
                    : "+f"(d[mt][nt][0]), "+f"(d[mt][nt][1]),
                      "+f"(d[mt][nt][2]), "+f"(d[mt][nt][3])
                    : "r"(a[mt][0]), "r"(a[mt][1]), "r"(a[mt][2]), "r"(a[mt][3]),
                      "r"(b[bi]), "r"(b[bi+1]));
            }
        }
    }

    #pragma unroll
    for (int mt = 0; mt < 4; mt++) {
        #pragma unroll
        for (int nt = 0; nt < 4; nt++) {
            float v0 = d[mt][nt][0], v1 = d[mt][nt][1];
            float v2 = d[mt][nt][2], v3 = d[mt][nt][3];
            #pragma unroll
            for (int off = 4; off <= 16; off <<= 1) {
                v0 = fmaxf(v0, __shfl_xor_sync(0xFFFFFFFFu, v0, off));
                v1 = fmaxf(v1, __shfl_xor_sync(0xFFFFFFFFu, v1, off));
                v2 = fmaxf(v2, __shfl_xor_sync(0xFFFFFFFFu, v2, off));
                v3 = fmaxf(v3, __shfl_xor_sync(0xFFFFFFFFu, v3, off));
            }
            if (lane < 4) {
                const int c = n0 + nt * 8 + lane * 2;
                const float2 bb = *(const float2*)(b2 + c);
                const int pA = p0 + mw * 8 + mt * 2;
                __half2 hA = __floats2half2_rn(fmaxf(v0 + bb.x, 0.0f),
                                               fmaxf(v1 + bb.y, 0.0f));
                __half2 hB = __floats2half2_rn(fmaxf(v2 + bb.x, 0.0f),
                                               fmaxf(v3 + bb.y, 0.0f));
                *(uint32_t*)(g_x1h + (size_t)(pA    ) * 128 + c) = *(uint32_t*)&hA;
                *(uint32_t*)(g_x1h + (size_t)(pA + 1) * 128 + c) = *(uint32_t*)&hB;
            }
        }
    }
}

// ---------------- Kernel 3: pre2 as fp16 GEMM, fp16 outputs -----------------
#define PADK 136
#define P_A_ELEMS (64  * PADK)
#define P_B_ELEMS (256 * PADK)
#define PRE2_SMEM ((P_A_ELEMS + P_B_ELEMS) * 2)

__global__ __launch_bounds__(256, 2) void pre2t_kernel(const float* __restrict__ b3)
{
    extern __shared__ __align__(16) char smem[];
    __half* sA = (__half*)smem;
    __half* sB = sA + P_A_ELEMS;

    const int t    = threadIdx.x;
    const int lane = t & 31;
    const int w    = t >> 5;
    const int i0   = blockIdx.x * 64;

    {
        const int r = t >> 2, q = t & 3;
        #pragma unroll
        for (int g = 0; g < 4; g++) {
            uint4 v = *((const uint4*)(g_x1h + (size_t)(i0 + r) * 128) + q*4 + g);
            *((uint4*)(sA + r * PADK) + q*4 + g) = v;
        }
    }
    {
        const uint4* s4 = (const uint4*)(g_w3h + (size_t)t * 128);
        uint4* d4 = (uint4*)(sB + t * PADK);
        #pragma unroll
        for (int kg = 0; kg < 16; kg++) d4[kg] = s4[kg];
    }
    __syncthreads();

    const int mw  = w & 1;
    const int nwp = w >> 1;
    const int m0  = mw * 32;
    const int n0  = nwp * 64;

    const uint32_t sA32 = smem_u32(sA), sB32 = smem_u32(sB);
    const uint32_t aoff = ((uint32_t)(m0 + (lane & 15)) * PADK +
                           ((lane >> 4) & 1) * 8) * 2;
    const uint32_t boff = ((uint32_t)(n0 + ((lane >> 4) & 1) * 8 + (lane & 7)) * PADK +
                           ((lane >> 3) & 1) * 8) * 2;

    float d[2][8][4];
    #pragma unroll
    for (int mt = 0; mt < 2; mt++)
        #pragma unroll
        for (int nt = 0; nt < 8; nt++)
            { d[mt][nt][0]=0.f; d[mt][nt][1]=0.f; d[mt][nt][2]=0.f; d[mt][nt][3]=0.f; }

    #pragma unroll
    for (int k16 = 0; k16 < 8; k16++) {
        const uint32_t kb = k16 * 32;
        uint32_t a[2][4];
        #pragma unroll
        for (int mt = 0; mt < 2; mt++) {
            asm volatile(
                "ldmatrix.sync.aligned.m8n8.x4.shared.b16 {%0,%1,%2,%3}, [%4];"
                : "=r"(a[mt][0]), "=r"(a[mt][1]), "=r"(a[mt][2]), "=r"(a[mt][3])
                : "r"(sA32 + aoff + (uint32_t)mt * (16 * PADK * 2) + kb));
        }
        uint32_t b[16];
        #pragma unroll
        for (int ntp = 0; ntp < 4; ntp++) {
            asm volatile(
                "ldmatrix.sync.aligned.m8n8.x4.shared.b16 {%0,%1,%2,%3}, [%4];"
                : "=r"(b[ntp*4]), "=r"(b[ntp*4+1]), "=r"(b[ntp*4+2]), "=r"(b[ntp*4+3])
                : "r"(sB32 + boff + (uint32_t)ntp * (16 * PADK * 2) + kb));
        }
        #pragma unroll
        for (int mt = 0; mt < 2; mt++) {
            #pragma unroll
            for (int nt = 0; nt < 8; nt++) {
                const int bi = (nt >> 1) * 4 + (nt & 1) * 2;
                asm volatile(
                    "mma.sync.aligned.m16n8k16.row.col.f32.f16.f16.f32 "
                    "{%0,%1,%2,%3}, {%4,%5,%6,%7}, {%8,%9}, {%0,%1,%2,%3};"
                    : "+f"(d[mt][nt][0]), "+f"(d[mt][nt][1]),
                      "+f"(d[mt][nt][2]), "+f"(d[mt][nt][3])
                    : "r"(a[mt][0]), "r"(a[mt][1]), "r"(a[mt][2]), "r"(a[mt][3]),
                      "r"(b[bi]), "r"(b[bi+1]));
            }
        }
    }

    #pragma unroll
    for (int mt = 0; mt < 2; mt++) {
        const int r0 = m0 + mt*16 + (lane >> 2);
        const int iAr = i0 + r0, iBr = i0 + r0 + 8;
        #pragma unroll
        for (int nt = 0; nt < 8; nt++) {
            const int c = n0 + nt * 8 + (lane & 3) * 2;
            if (c < 128) {
                const float2 bb = *(const float2*)(b3 + c);
                __half2 h0 = __floats2half2_rn(d[mt][nt][0] + bb.x,
                                               d[mt][nt][1] + bb.y);
                __half2 h1 = __floats2half2_rn(d[mt][nt][2] + bb.x,
                                               d[mt][nt][3] + bb.y);
                *(uint32_t*)(g_Ah + (size_t)iAr * 128 + c) = *(uint32_t*)&h0;
                *(uint32_t*)(g_Ah + (size_t)iBr * 128 + c) = *(uint32_t*)&h1;
            } else {
                __half2 h0 = __floats2half2_rn(d[mt][nt][0], d[mt][nt][1]);
                __half2 h1 = __floats2half2_rn(d[mt][nt][2], d[mt][nt][3]);
                *(uint32_t*)(g_Bh + (size_t)iAr * 128 + (c - 128)) = *(uint32_t*)&h0;
                *(uint32_t*)(g_Bh + (size_t)iBr * 128 + (c - 128)) = *(uint32_t*)&h1;
            }
        }
    }
}

// ---------------- Kernel 4: EdgeConv2 fp16 mma, M=128/CTA, 512 thr ----------
#define A_ELEMS (128 * PADK)
#define B_ELEMS (256 * PADK)
#define CONV2_SMEM ((A_ELEMS + B_ELEMS) * 2)

__global__ __launch_bounds__(512, 1) void conv2m_kernel(
    const float* __restrict__ b4, float* __restrict__ out)
{
    extern __shared__ __align__(16) char smem[];
    __half* sA = (__half*)smem;
    __half* sB = sA + A_ELEMS;

    const int t    = threadIdx.x;
    const int lane = t & 31;
    const int w    = t >> 5;
    const int p0   = blockIdx.x * 16;

    {
        const int row = t >> 1, part = (t & 1) * 8;
        const uint4* s4 = (const uint4*)(g_w4h + (size_t)row * 128);
        uint4* d4 = (uint4*)(sB + row * PADK);
        #pragma unroll
        for (int g = 0; g < 8; g++) d4[part + g] = s4[part + g];
    }
    {
        const int r = t >> 2, q = t & 3;
        const int i = p0 + (r >> 3);
        const int j = g_knn[i * KNN + (r & 7)];
        const uint4* pa = (const uint4*)(g_Ah + (size_t)i * 128);
        const uint4* pb = (const uint4*)(g_Bh + (size_t)j * 128);
        uint4* dst = (uint4*)(sA + r * PADK);
        const __half2 z2 = __half2half2(__ushort_as_half(0));
        #pragma unroll
        for (int g = 0; g < 4; g++) {
            uint4 av = pa[q*4 + g];
            uint4 bv = pb[q*4 + g];
            uint4 o;
            __half2 s;
            s = __hmax2(__hadd2(*(__half2*)&av.x, *(__half2*)&bv.x), z2); o.x = *(uint32_t*)&s;
            s = __hmax2(__hadd2(*(__half2*)&av.y, *(__half2*)&bv.y), z2); o.y = *(uint32_t*)&s;
            s = __hmax2(__hadd2(*(__half2*)&av.z, *(__half2*)&bv.z), z2); o.z = *(uint32_t*)&s;
            s = __hmax2(__hadd2(*(__half2*)&av.w, *(__half2*)&bv.w), z2); o.w = *(uint32_t*)&s;
            dst[q*4 + g] = o;
        }
    }
    __syncthreads();

    const int mw  = w & 3;
    const int nwp = w >> 2;
    const int m0  = mw * 32;
    const int n0  = nwp * 64;

    const uint32_t sA32 = smem_u32(sA), sB32 = smem_u32(sB);
    const uint32_t aoff = ((uint32_t)(m0 + (lane & 15)) * PADK +
                           ((lane >> 4) & 1) * 8) * 2;
    const uint32_t boff = ((uint32_t)(n0 + ((lane >> 4) & 1) * 8 + (lane & 7)) * PADK +
                           ((lane >> 3) & 1) * 8) * 2;

    float d[2][8][4];
    #pragma unroll
    for (int mt = 0; mt < 2; mt++)
        #pragma unroll
        for (int nt = 0; nt < 8; nt++)
            { d[mt][nt][0]=0.f; d[mt][nt][1]=0.f; d[mt][nt][2]=0.f; d[mt][nt][3]=0.f; }

    #pragma unroll
    for (int k16 = 0; k16 < 8; k16++) {
        const uint32_t kb = k16 * 32;
        uint32_t a[2][4];
        #pragma unroll
        for (int mt = 0; mt < 2; mt++) {
            asm volatile(
                "ldmatrix.sync.aligned.m8n8.x4.shared.b16 {%0,%1,%2,%3}, [%4];"
                : "=r"(a[mt][0]), "=r"(a[mt][1]), "=r"(a[mt][2]), "=r"(a[mt][3])
                : "r"(sA32 + aoff + (uint32_t)mt * (16 * PADK * 2) + kb));
        }
        uint32_t b[16];
        #pragma unroll
        for (int ntp = 0; ntp < 4; ntp++) {
            asm volatile(
                "ldmatrix.sync.aligned.m8n8.x4.shared.b16 {%0,%1,%2,%3}, [%4];"
                : "=r"(b[ntp*4]), "=r"(b[ntp*4+1]), "=r"(b[ntp*4+2]), "=r"(b[ntp*4+3])
                : "r"(sB32 + boff + (uint32_t)ntp * (16 * PADK * 2) + kb));
        }
        #pragma unroll
        for (int mt = 0; mt < 2; mt++) {
            #pragma unroll
            for (int nt = 0; nt < 8; nt++) {
                const int bi = (nt >> 1) * 4 + (nt & 1) * 2;
                asm volatile(
                    "mma.sync.aligned.m16n8k16.row.col.f32.f16.f16.f32 "
                    "{%0,%1,%2,%3}, {%4,%5,%6,%7}, {%8,%9}, {%0,%1,%2,%3};"
                    : "+f"(d[mt][nt][0]), "+f"(d[mt][nt][1]),
                      "+f"(d[mt][nt][2]), "+f"(d[mt][nt][3])
                    : "r"(a[mt][0]), "r"(a[mt][1]), "r"(a[mt][2]), "r"(a[mt][3]),
                      "r"(b[bi]), "r"(b[bi+1]));
            }
        }
    }

    #pragma unroll
    for (int mt = 0; mt < 2; mt++) {
        #pragma unroll
        for (int nt = 0; nt < 8; nt++) {
            float v0 = d[mt][nt][0], v1 = d[mt][nt][1];
            float v2 = d[mt][nt][2], v3 = d[mt][nt][3];
            #pragma unroll
            for (int off = 4; off <= 16; off <<= 1) {
                v0 = fmaxf(v0, __shfl_xor_sync(0xFFFFFFFFu, v0, off));
                v1 = fmaxf(v1, __shfl_xor_sync(0xFFFFFFFFu, v1, off));
                v2 = fmaxf(v2, __shfl_xor_sync(0xFFFFFFFFu, v2, off));
                v3 = fmaxf(v3, __shfl_xor_sync(0xFFFFFFFFu, v3, off));
            }
            if (lane < 4) {
                const int c = n0 + nt * 8 + lane * 2;
                const float2 bb = *(const float2*)(b4 + c);
                const int pbase = p0 + mw * 4 + mt * 2;
                float2 o0; o0.x = v0 + bb.x; o0.y = v1 + bb.y;
                float2 o1; o1.x = v2 + bb.x; o1.y = v3 + bb.y;
                *(float2*)(out + (size_t)(pbase    ) * 256 + c) = o0;
                *(float2*)(out + (size_t)(pbase + 1) * 256 + c) = o1;
            }
        }
    }
}

// ---------------- launch -----------------------------------------------------
extern "C" void kernel_launch(void* const* d_in, const int* in_sizes, int n_in,
                              void* d_out, int out_size) {
    const float* pts = (const float*)d_in[0];
    const float* W1  = (const float*)d_in[1];
    const float* b1  = (const float*)d_in[2];
    const float* W2  = (const float*)d_in[3];
    const float* b2  = (const float*)d_in[4];
    const float* W3  = (const float*)d_in[5];
    const float* b3  = (const float*)d_in[6];
    const float* W4  = (const float*)d_in[7];
    const float* b4  = (const float*)d_in[8];
    float* out = (float*)d_out;

    cudaFuncSetAttribute(pre2t_kernel,
                         cudaFuncAttributeMaxDynamicSharedMemorySize, PRE2_SMEM);
    cudaFuncSetAttribute(conv2m_kernel,
                         cudaFuncAttributeMaxDynamicSharedMemorySize, CONV2_SMEM);

    w2conv_kernel<<<32, 256>>>(W2);
    w3conv_kernel<<<64, 256>>>(W3);
    w4conv_kernel<<<128, 256>>>(W4);
    knn_kernel   <<<NPTS/8, 256>>>(pts);     // 4th launch -> profiled
    conv1_kernel <<<NPTS/16, 256>>>(pts, W1, b1, b2);
    pre2t_kernel <<<NPTS/64, 256, PRE2_SMEM>>>(b3);
    conv2m_kernel<<<NPTS/16, 512, CONV2_SMEM>>>(b4, out);
}